// round 1
// baseline (speedup 1.0000x reference)
#include <cuda_runtime.h>

#define NB 4
#define C  256
#define NS 4096   // H*W = 64*64 spatial positions

// ---- device scratch (allocation-free per harness rules) ----
__device__ float g_T[NB * C * NS];                 // theta, (C, NS) per batch
__device__ float g_P[NB * C * NS];                 // phi
__device__ float g_G[NB * C * NS];                 // g
__device__ float g_Y[NB * C * NS];                 // attention output (C, NS)
__device__ float g_S[(size_t)NB * NS * NS];        // logits / softmax weights, 256 MB

// ============================================================================
// Kernel 1: projections.  Out(which) = W(which) @ X + b, per batch.
// A = W [M=256, K=256] row-major; B = X [K=256, N=4096] row-major.
// ============================================================================
__global__ void proj_kernel(const float* __restrict__ x,
                            const float* __restrict__ Wg, const float* __restrict__ bg,
                            const float* __restrict__ Wt, const float* __restrict__ bt,
                            const float* __restrict__ Wp, const float* __restrict__ bp)
{
    const int BM = 64, BN = 64, BK = 16;
    int z = blockIdx.z;
    int batch = z / 3, which = z % 3;
    const float* W = (which == 0) ? Wg : (which == 1) ? Wt : Wp;
    const float* b = (which == 0) ? bg : (which == 1) ? bt : bp;
    float* Out = ((which == 0) ? g_G : (which == 1) ? g_T : g_P) + batch * C * NS;
    const float* X = x + batch * C * NS;

    __shared__ float As[BK][BM + 4];   // padded: transposed scatter stores
    __shared__ float Bs[BK][BN];

    int tid = threadIdx.x;            // 256 threads
    int tx = tid % 16, ty = tid / 16;
    int m0 = blockIdx.y * BM;
    int n0 = blockIdx.x * BN;

    float acc[4][4] = {};
    for (int kt = 0; kt < C; kt += BK) {
        // A tile: W[m0+r][kt+c4..c4+3], transpose into As[k][m]
        {
            int r = tid / 4, c4 = (tid % 4) * 4;
            float4 v = *(const float4*)&W[(m0 + r) * C + kt + c4];
            As[c4 + 0][r] = v.x; As[c4 + 1][r] = v.y;
            As[c4 + 2][r] = v.z; As[c4 + 3][r] = v.w;
        }
        // B tile: X[kt+r][n0+c4..], direct
        {
            int r = tid / 16, c4 = (tid % 16) * 4;
            *(float4*)&Bs[r][c4] = *(const float4*)&X[(kt + r) * NS + n0 + c4];
        }
        __syncthreads();
        #pragma unroll
        for (int kk = 0; kk < BK; kk++) {
            float4 a4 = *(float4*)&As[kk][ty * 4];
            float4 b4 = *(float4*)&Bs[kk][tx * 4];
            float av[4] = {a4.x, a4.y, a4.z, a4.w};
            float bv[4] = {b4.x, b4.y, b4.z, b4.w};
            #pragma unroll
            for (int i = 0; i < 4; i++)
                #pragma unroll
                for (int j = 0; j < 4; j++)
                    acc[i][j] += av[i] * bv[j];
        }
        __syncthreads();
    }
    #pragma unroll
    for (int i = 0; i < 4; i++) {
        int m = m0 + ty * 4 + i;
        float bias = b[m];
        #pragma unroll
        for (int j = 0; j < 4; j++)
            Out[m * NS + n0 + tx * 4 + j] = acc[i][j] + bias;
    }
}

// ============================================================================
// Kernel 2: logits[q][k] = sum_c Tc[c][q] * Pc[c][k].
// Both operands are [K=256, M/N=4096] — K is the slow dim, loads are coalesced.
// ============================================================================
__global__ void logits_kernel()
{
    const int BM = 64, BN = 64, BK = 16;
    int batch = blockIdx.z;
    const float* A = g_T + batch * C * NS;   // [k][q], ld NS
    const float* B = g_P + batch * C * NS;   // [k][k'], ld NS
    float* Out = g_S + (size_t)batch * NS * NS;

    __shared__ float As[BK][BM];
    __shared__ float Bs[BK][BN];

    int tid = threadIdx.x;
    int tx = tid % 16, ty = tid / 16;
    int m0 = blockIdx.y * BM;
    int n0 = blockIdx.x * BN;

    float acc[4][4] = {};
    for (int kt = 0; kt < C; kt += BK) {
        {
            int r = tid / 16, c4 = (tid % 16) * 4;
            *(float4*)&As[r][c4] = *(const float4*)&A[(kt + r) * NS + m0 + c4];
            *(float4*)&Bs[r][c4] = *(const float4*)&B[(kt + r) * NS + n0 + c4];
        }
        __syncthreads();
        #pragma unroll
        for (int kk = 0; kk < BK; kk++) {
            float4 a4 = *(float4*)&As[kk][ty * 4];
            float4 b4 = *(float4*)&Bs[kk][tx * 4];
            float av[4] = {a4.x, a4.y, a4.z, a4.w};
            float bv[4] = {b4.x, b4.y, b4.z, b4.w};
            #pragma unroll
            for (int i = 0; i < 4; i++)
                #pragma unroll
                for (int j = 0; j < 4; j++)
                    acc[i][j] += av[i] * bv[j];
        }
        __syncthreads();
    }
    #pragma unroll
    for (int i = 0; i < 4; i++) {
        size_t m = m0 + ty * 4 + i;
        #pragma unroll
        for (int j = 0; j < 4; j++)
            Out[m * NS + n0 + tx * 4 + j] = acc[i][j];
    }
}

// ============================================================================
// Kernel 3: row softmax over g_S (NB*NS rows of length NS).
// One block (256 threads) per row; each thread holds 16 values in registers.
// ============================================================================
__global__ void softmax_kernel()
{
    size_t row = blockIdx.x;
    float* p = g_S + row * (size_t)NS;
    int tid = threadIdx.x;
    int lane = tid & 31, wid = tid >> 5;
    __shared__ float red[8];

    float4 v[4];
    float mx = -1e30f;
    #pragma unroll
    for (int i = 0; i < 4; i++) {
        v[i] = *(const float4*)&p[(tid + i * 256) * 4];
        mx = fmaxf(mx, fmaxf(fmaxf(v[i].x, v[i].y), fmaxf(v[i].z, v[i].w)));
    }
    #pragma unroll
    for (int off = 16; off > 0; off >>= 1)
        mx = fmaxf(mx, __shfl_xor_sync(0xffffffffu, mx, off));
    if (lane == 0) red[wid] = mx;
    __syncthreads();
    mx = red[0];
    #pragma unroll
    for (int w = 1; w < 8; w++) mx = fmaxf(mx, red[w]);

    float s = 0.f;
    #pragma unroll
    for (int i = 0; i < 4; i++) {
        v[i].x = expf(v[i].x - mx); v[i].y = expf(v[i].y - mx);
        v[i].z = expf(v[i].z - mx); v[i].w = expf(v[i].w - mx);
        s += v[i].x + v[i].y + v[i].z + v[i].w;
    }
    #pragma unroll
    for (int off = 16; off > 0; off >>= 1)
        s += __shfl_xor_sync(0xffffffffu, s, off);
    __syncthreads();                    // red reuse guard
    if (lane == 0) red[wid] = s;
    __syncthreads();
    s = 0.f;
    #pragma unroll
    for (int w = 0; w < 8; w++) s += red[w];
    float inv = 1.0f / s;

    #pragma unroll
    for (int i = 0; i < 4; i++) {
        v[i].x *= inv; v[i].y *= inv; v[i].z *= inv; v[i].w *= inv;
        *(float4*)&p[(tid + i * 256) * 4] = v[i];
    }
}

// ============================================================================
// Kernel 4: Yc[c][q] = sum_k Gc[c][k] * PW[q][k].   (A·B^T, K=4096)
// ============================================================================
__global__ void av_kernel()
{
    const int BM = 64, BN = 64, BK = 16;
    int batch = blockIdx.z;
    const float* A = g_G + batch * C * NS;               // [c][k] ld NS
    const float* B = g_S + (size_t)batch * NS * NS;      // pw [q][k] ld NS
    float* Out = g_Y + batch * C * NS;                   // [c][q]

    __shared__ float As[BK][BM + 4];
    __shared__ float Bs[BK][BN + 4];

    int tid = threadIdx.x;
    int tx = tid % 16, ty = tid / 16;
    int m0 = blockIdx.y * BM;   // c
    int n0 = blockIdx.x * BN;   // q

    float acc[4][4] = {};
    for (int kt = 0; kt < NS; kt += BK) {
        int r = tid / 4, c4 = (tid % 4) * 4;
        {
            float4 va = *(const float4*)&A[(m0 + r) * NS + kt + c4];
            As[c4 + 0][r] = va.x; As[c4 + 1][r] = va.y;
            As[c4 + 2][r] = va.z; As[c4 + 3][r] = va.w;
            float4 vb = *(const float4*)&B[(size_t)(n0 + r) * NS + kt + c4];
            Bs[c4 + 0][r] = vb.x; Bs[c4 + 1][r] = vb.y;
            Bs[c4 + 2][r] = vb.z; Bs[c4 + 3][r] = vb.w;
        }
        __syncthreads();
        #pragma unroll
        for (int kk = 0; kk < BK; kk++) {
            float4 a4 = *(float4*)&As[kk][ty * 4];
            float4 b4 = *(float4*)&Bs[kk][tx * 4];
            float av[4] = {a4.x, a4.y, a4.z, a4.w};
            float bv[4] = {b4.x, b4.y, b4.z, b4.w};
            #pragma unroll
            for (int i = 0; i < 4; i++)
                #pragma unroll
                for (int j = 0; j < 4; j++)
                    acc[i][j] += av[i] * bv[j];
        }
        __syncthreads();
    }
    #pragma unroll
    for (int i = 0; i < 4; i++)
        #pragma unroll
        for (int j = 0; j < 4; j++)
            Out[(m0 + ty * 4 + i) * NS + n0 + tx * 4 + j] = acc[i][j];
}

// ============================================================================
// Kernel 5: out = x + Wo @ Yc + bo (residual fused).
// ============================================================================
__global__ void out_kernel(const float* __restrict__ x,
                           const float* __restrict__ Wo,
                           const float* __restrict__ bo,
                           float* __restrict__ out)
{
    const int BM = 64, BN = 64, BK = 16;
    int batch = blockIdx.z;
    const float* B = g_Y + batch * C * NS;   // [c][q] ld NS
    const float* Xr = x + batch * C * NS;
    float* O = out + batch * C * NS;

    __shared__ float As[BK][BM + 4];
    __shared__ float Bs[BK][BN];

    int tid = threadIdx.x;
    int tx = tid % 16, ty = tid / 16;
    int m0 = blockIdx.y * BM;
    int n0 = blockIdx.x * BN;

    float acc[4][4] = {};
    for (int kt = 0; kt < C; kt += BK) {
        {
            int r = tid / 4, c4 = (tid % 4) * 4;
            float4 v = *(const float4*)&Wo[(m0 + r) * C + kt + c4];
            As[c4 + 0][r] = v.x; As[c4 + 1][r] = v.y;
            As[c4 + 2][r] = v.z; As[c4 + 3][r] = v.w;
        }
        {
            int r = tid / 16, c4 = (tid % 16) * 4;
            *(float4*)&Bs[r][c4] = *(const float4*)&B[(kt + r) * NS + n0 + c4];
        }
        __syncthreads();
        #pragma unroll
        for (int kk = 0; kk < BK; kk++) {
            float4 a4 = *(float4*)&As[kk][ty * 4];
            float4 b4 = *(float4*)&Bs[kk][tx * 4];
            float av[4] = {a4.x, a4.y, a4.z, a4.w};
            float bv[4] = {b4.x, b4.y, b4.z, b4.w};
            #pragma unroll
            for (int i = 0; i < 4; i++)
                #pragma unroll
                for (int j = 0; j < 4; j++)
                    acc[i][j] += av[i] * bv[j];
        }
        __syncthreads();
    }
    #pragma unroll
    for (int i = 0; i < 4; i++) {
        int m = m0 + ty * 4 + i;
        float bias = bo[m];
        #pragma unroll
        for (int j = 0; j < 4; j++) {
            int n = n0 + tx * 4 + j;
            O[m * NS + n] = acc[i][j] + bias + Xr[m * NS + n];
        }
    }
}

// ============================================================================
extern "C" void kernel_launch(void* const* d_in, const int* in_sizes, int n_in,
                              void* d_out, int out_size)
{
    const float* x  = (const float*)d_in[0];
    const float* Wg = (const float*)d_in[1];
    const float* bg = (const float*)d_in[2];
    const float* Wt = (const float*)d_in[3];
    const float* bt = (const float*)d_in[4];
    const float* Wp = (const float*)d_in[5];
    const float* bp = (const float*)d_in[6];
    const float* Wo = (const float*)d_in[7];
    const float* bo = (const float*)d_in[8];
    float* out = (float*)d_out;

    proj_kernel  <<<dim3(NS / 64, C  / 64, NB * 3), 256>>>(x, Wg, bg, Wt, bt, Wp, bp);
    logits_kernel<<<dim3(NS / 64, NS / 64, NB),     256>>>();
    softmax_kernel<<<NB * NS, 256>>>();
    av_kernel    <<<dim3(NS / 64, C  / 64, NB),     256>>>();
    out_kernel   <<<dim3(NS / 64, C  / 64, NB),     256>>>(x, Wo, bo, out);
}

// round 2
// speedup vs baseline: 1.3352x; 1.3352x over previous
#include <cuda_runtime.h>

#define NB 4
#define C  256
#define NS 4096   // H*W

// ---- device scratch (allocation-free per harness rules) ----
__device__ float g_T[NB * C * NS];
__device__ float g_P[NB * C * NS];
__device__ float g_G[NB * C * NS];
__device__ float g_Y[NB * C * NS];
__device__ float g_S[(size_t)NB * NS * NS];   // 256 MB logits / softmax weights

#define SROW 132   // 128 + 4 pad (keeps float4 row alignment: 132*4=528B)

// ============================================================================
// Shared 128x128x(K) GEMM tile body. 256 threads, 8x8 micro-tile per thread.
// TA: 0 -> A stored [k][m] (K-major, direct copy); 1 -> A stored [m][k] (transpose load)
// TB: 0 -> B stored [k][n];                        1 -> B stored [n][k]
// ============================================================================
template<int TA, int TB>
__device__ __forceinline__ void gemm_tile(
    const float* __restrict__ A, int lda,
    const float* __restrict__ B, int ldb,
    int K, int m0, int n0, float acc[8][8])
{
    __shared__ float As[16][SROW];
    __shared__ float Bs[16][SROW];
    const int tid = threadIdx.x;
    const int tx = tid & 15, ty = tid >> 4;

    float4 a0, a1, b0, b1;

    // ---- global loaders (2 float4 per thread per operand) ----
    auto loadA = [&](int kt) {
        if (TA == 0) {
            int r = tid >> 4, c = (tid & 15) * 8;
            const float* p = &A[(size_t)(kt + r) * lda + m0 + c];
            a0 = *(const float4*)p; a1 = *(const float4*)(p + 4);
        } else {
            int m = tid >> 1, k4 = (tid & 1) * 8;
            const float* p = &A[(size_t)(m0 + m) * lda + kt + k4];
            a0 = *(const float4*)p; a1 = *(const float4*)(p + 4);
        }
    };
    auto loadB = [&](int kt) {
        if (TB == 0) {
            int r = tid >> 4, c = (tid & 15) * 8;
            const float* p = &B[(size_t)(kt + r) * ldb + n0 + c];
            b0 = *(const float4*)p; b1 = *(const float4*)(p + 4);
        } else {
            int n = tid >> 1, k4 = (tid & 1) * 8;
            const float* p = &B[(size_t)(n0 + n) * ldb + kt + k4];
            b0 = *(const float4*)p; b1 = *(const float4*)(p + 4);
        }
    };
    auto storeA = [&]() {
        if (TA == 0) {
            int r = tid >> 4, c = (tid & 15) * 8;
            *(float4*)&As[r][c] = a0; *(float4*)&As[r][c + 4] = a1;
        } else {
            int m = tid >> 1, k4 = (tid & 1) * 8;
            As[k4 + 0][m] = a0.x; As[k4 + 1][m] = a0.y;
            As[k4 + 2][m] = a0.z; As[k4 + 3][m] = a0.w;
            As[k4 + 4][m] = a1.x; As[k4 + 5][m] = a1.y;
            As[k4 + 6][m] = a1.z; As[k4 + 7][m] = a1.w;
        }
    };
    auto storeB = [&]() {
        if (TB == 0) {
            int r = tid >> 4, c = (tid & 15) * 8;
            *(float4*)&Bs[r][c] = b0; *(float4*)&Bs[r][c + 4] = b1;
        } else {
            int n = tid >> 1, k4 = (tid & 1) * 8;
            Bs[k4 + 0][n] = b0.x; Bs[k4 + 1][n] = b0.y;
            Bs[k4 + 2][n] = b0.z; Bs[k4 + 3][n] = b0.w;
            Bs[k4 + 4][n] = b1.x; Bs[k4 + 5][n] = b1.y;
            Bs[k4 + 6][n] = b1.z; Bs[k4 + 7][n] = b1.w;
        }
    };

    loadA(0); loadB(0);
    storeA(); storeB();
    __syncthreads();

    for (int kt = 0; kt < K; kt += 16) {
        bool more = (kt + 16) < K;
        if (more) { loadA(kt + 16); loadB(kt + 16); }   // prefetch to regs
        #pragma unroll
        for (int kk = 0; kk < 16; kk++) {
            float av[8], bv[8];
            *(float4*)&av[0] = *(const float4*)&As[kk][ty * 4];
            *(float4*)&av[4] = *(const float4*)&As[kk][64 + ty * 4];
            *(float4*)&bv[0] = *(const float4*)&Bs[kk][tx * 4];
            *(float4*)&bv[4] = *(const float4*)&Bs[kk][64 + tx * 4];
            #pragma unroll
            for (int i = 0; i < 8; i++)
                #pragma unroll
                for (int j = 0; j < 8; j++)
                    acc[i][j] += av[i] * bv[j];
        }
        __syncthreads();
        if (more) { storeA(); storeB(); __syncthreads(); }
    }
}

// row/col of acc element (i in 0..7): rows m0 + (i>=4)*64 + ty*4 + (i&3)
#define ACC_M(i) (m0 + ((i) >= 4 ? 64 : 0) + ty * 4 + ((i) & 3))
#define ACC_N(j) (n0 + ((j) >= 4 ? 64 : 0) + tx * 4 + ((j) & 3))

// ============================================================================
// Kernel 1: projections G/T/P = W @ X + b
// ============================================================================
__global__ void __launch_bounds__(256, 2)
proj_kernel(const float* __restrict__ x,
            const float* __restrict__ Wg, const float* __restrict__ bg,
            const float* __restrict__ Wt, const float* __restrict__ bt,
            const float* __restrict__ Wp, const float* __restrict__ bp)
{
    int z = blockIdx.z;
    int batch = z / 3, which = z % 3;
    const float* W = (which == 0) ? Wg : (which == 1) ? Wt : Wp;
    const float* b = (which == 0) ? bg : (which == 1) ? bt : bp;
    float* Out = ((which == 0) ? g_G : (which == 1) ? g_T : g_P) + batch * C * NS;
    const float* X = x + batch * C * NS;

    int m0 = blockIdx.y * 128, n0 = blockIdx.x * 128;
    int tx = threadIdx.x & 15, ty = threadIdx.x >> 4;
    float acc[8][8] = {};
    gemm_tile<1, 0>(W, C, X, NS, C, m0, n0, acc);

    #pragma unroll
    for (int i = 0; i < 8; i++) {
        int m = ACC_M(i);
        float bias = b[m];
        #pragma unroll
        for (int jj = 0; jj < 2; jj++) {
            int n = n0 + jj * 64 + tx * 4;
            float4 r = {acc[i][jj*4+0] + bias, acc[i][jj*4+1] + bias,
                        acc[i][jj*4+2] + bias, acc[i][jj*4+3] + bias};
            *(float4*)&Out[(size_t)m * NS + n] = r;
        }
    }
}

// ============================================================================
// Kernel 2: logits = T^T @ P (both K-major)
// ============================================================================
__global__ void __launch_bounds__(256, 2)
logits_kernel()
{
    int batch = blockIdx.z;
    const float* A = g_T + batch * C * NS;
    const float* B = g_P + batch * C * NS;
    float* Out = g_S + (size_t)batch * NS * NS;

    int m0 = blockIdx.y * 128, n0 = blockIdx.x * 128;
    int tx = threadIdx.x & 15, ty = threadIdx.x >> 4;
    float acc[8][8] = {};
    gemm_tile<0, 0>(A, NS, B, NS, C, m0, n0, acc);

    #pragma unroll
    for (int i = 0; i < 8; i++) {
        size_t m = ACC_M(i);
        #pragma unroll
        for (int jj = 0; jj < 2; jj++) {
            int n = n0 + jj * 64 + tx * 4;
            float4 r = {acc[i][jj*4+0], acc[i][jj*4+1], acc[i][jj*4+2], acc[i][jj*4+3]};
            *(float4*)&Out[m * NS + n] = r;
        }
    }
}

// ============================================================================
// Kernel 3: row softmax (one block per row, 16 values/thread in registers)
// ============================================================================
__global__ void softmax_kernel()
{
    size_t row = blockIdx.x;
    float* p = g_S + row * (size_t)NS;
    int tid = threadIdx.x;
    int lane = tid & 31, wid = tid >> 5;
    __shared__ float red[8];

    float4 v[4];
    float mx = -1e30f;
    #pragma unroll
    for (int i = 0; i < 4; i++) {
        v[i] = *(const float4*)&p[(tid + i * 256) * 4];
        mx = fmaxf(mx, fmaxf(fmaxf(v[i].x, v[i].y), fmaxf(v[i].z, v[i].w)));
    }
    #pragma unroll
    for (int off = 16; off > 0; off >>= 1)
        mx = fmaxf(mx, __shfl_xor_sync(0xffffffffu, mx, off));
    if (lane == 0) red[wid] = mx;
    __syncthreads();
    mx = red[0];
    #pragma unroll
    for (int w = 1; w < 8; w++) mx = fmaxf(mx, red[w]);

    float s = 0.f;
    #pragma unroll
    for (int i = 0; i < 4; i++) {
        v[i].x = expf(v[i].x - mx); v[i].y = expf(v[i].y - mx);
        v[i].z = expf(v[i].z - mx); v[i].w = expf(v[i].w - mx);
        s += v[i].x + v[i].y + v[i].z + v[i].w;
    }
    #pragma unroll
    for (int off = 16; off > 0; off >>= 1)
        s += __shfl_xor_sync(0xffffffffu, s, off);
    __syncthreads();
    if (lane == 0) red[wid] = s;
    __syncthreads();
    s = 0.f;
    #pragma unroll
    for (int w = 0; w < 8; w++) s += red[w];
    float inv = 1.0f / s;

    #pragma unroll
    for (int i = 0; i < 4; i++) {
        v[i].x *= inv; v[i].y *= inv; v[i].z *= inv; v[i].w *= inv;
        *(float4*)&p[(tid + i * 256) * 4] = v[i];
    }
}

// ============================================================================
// Kernel 4: Y[c][q] = sum_k G[c][k] * PW[q][k]   (both M/N-major, K=4096)
// ============================================================================
__global__ void __launch_bounds__(256, 2)
av_kernel()
{
    int batch = blockIdx.z;
    const float* A = g_G + batch * C * NS;
    const float* B = g_S + (size_t)batch * NS * NS;
    float* Out = g_Y + batch * C * NS;

    int m0 = blockIdx.y * 128, n0 = blockIdx.x * 128;
    int tx = threadIdx.x & 15, ty = threadIdx.x >> 4;
    float acc[8][8] = {};
    gemm_tile<1, 1>(A, NS, B, NS, NS, m0, n0, acc);

    #pragma unroll
    for (int i = 0; i < 8; i++) {
        int m = ACC_M(i);
        #pragma unroll
        for (int jj = 0; jj < 2; jj++) {
            int n = n0 + jj * 64 + tx * 4;
            float4 r = {acc[i][jj*4+0], acc[i][jj*4+1], acc[i][jj*4+2], acc[i][jj*4+3]};
            *(float4*)&Out[(size_t)m * NS + n] = r;
        }
    }
}

// ============================================================================
// Kernel 5: out = x + Wo @ Y + bo
// ============================================================================
__global__ void __launch_bounds__(256, 2)
out_kernel(const float* __restrict__ x,
           const float* __restrict__ Wo,
           const float* __restrict__ bo,
           float* __restrict__ out)
{
    int batch = blockIdx.z;
    const float* B = g_Y + batch * C * NS;
    const float* Xr = x + batch * C * NS;
    float* O = out + batch * C * NS;

    int m0 = blockIdx.y * 128, n0 = blockIdx.x * 128;
    int tx = threadIdx.x & 15, ty = threadIdx.x >> 4;
    float acc[8][8] = {};
    gemm_tile<1, 0>(Wo, C, B, NS, C, m0, n0, acc);

    #pragma unroll
    for (int i = 0; i < 8; i++) {
        int m = ACC_M(i);
        float bias = bo[m];
        #pragma unroll
        for (int jj = 0; jj < 2; jj++) {
            int n = n0 + jj * 64 + tx * 4;
            float4 xr = *(const float4*)&Xr[(size_t)m * NS + n];
            float4 r = {acc[i][jj*4+0] + bias + xr.x, acc[i][jj*4+1] + bias + xr.y,
                        acc[i][jj*4+2] + bias + xr.z, acc[i][jj*4+3] + bias + xr.w};
            *(float4*)&O[(size_t)m * NS + n] = r;
        }
    }
}

// ============================================================================
extern "C" void kernel_launch(void* const* d_in, const int* in_sizes, int n_in,
                              void* d_out, int out_size)
{
    const float* x  = (const float*)d_in[0];
    const float* Wg = (const float*)d_in[1];
    const float* bg = (const float*)d_in[2];
    const float* Wt = (const float*)d_in[3];
    const float* bt = (const float*)d_in[4];
    const float* Wp = (const float*)d_in[5];
    const float* bp = (const float*)d_in[6];
    const float* Wo = (const float*)d_in[7];
    const float* bo = (const float*)d_in[8];
    float* out = (float*)d_out;

    proj_kernel  <<<dim3(NS / 128, C  / 128, NB * 3), 256>>>(x, Wg, bg, Wt, bt, Wp, bp);
    logits_kernel<<<dim3(NS / 128, NS / 128, NB),     256>>>();
    softmax_kernel<<<NB * NS, 256>>>();
    av_kernel    <<<dim3(NS / 128, C  / 128, NB),     256>>>();
    out_kernel   <<<dim3(NS / 128, C  / 128, NB),     256>>>(x, Wo, bo, out);
}

// round 4
// speedup vs baseline: 1.9804x; 1.4832x over previous
#include <cuda_runtime.h>
#include <cuda_bf16.h>

#define NB 4
#define C  256
#define NS 4096

// ---- device scratch (allocation-free per harness rules) ----
__device__ unsigned int g_T2[NB * NS * C];                 // theta [q][c], packed (hi<<16|lo) bf16
__device__ unsigned int g_P2[NB * NS * C];                 // phi   [k'][c]
__device__ unsigned int g_G2[NB * C * NS];                 // g     [c][k]
__device__ float        g_S [(size_t)NB * NS * NS];        // logits fp32
__device__ unsigned int g_PW2[(size_t)NB * NS * NS];       // softmax weights packed
__device__ float        g_Y [NB * C * NS];                 // attention out fp32 [c][q]

__device__ __forceinline__ unsigned smem_u32(const void* p) {
    unsigned a;
    asm("{ .reg .u64 t; cvta.to.shared.u64 t, %1; cvt.u32.u64 %0, t; }" : "=r"(a) : "l"(p));
    return a;
}

__device__ __forceinline__ unsigned pack_split(float v) {
    __nv_bfloat16 h = __float2bfloat16(v);
    float r = v - __bfloat162float(h);
    __nv_bfloat16 l = __float2bfloat16(r);
    return ((unsigned)__bfloat16_as_ushort(h) << 16) | (unsigned)__bfloat16_as_ushort(l);
}

__device__ __forceinline__ void ldsm_x4(unsigned addr, unsigned& r0, unsigned& r1,
                                        unsigned& r2, unsigned& r3) {
    asm volatile("ldmatrix.sync.aligned.m8n8.x4.shared.b16 {%0,%1,%2,%3}, [%4];"
                 : "=r"(r0), "=r"(r1), "=r"(r2), "=r"(r3) : "r"(addr));
}
__device__ __forceinline__ void mma16816(float* c, const unsigned* a, const unsigned* b) {
    asm volatile("mma.sync.aligned.m16n8k16.row.col.f32.bf16.bf16.f32 "
                 "{%0,%1,%2,%3}, {%4,%5,%6,%7}, {%8,%9}, {%0,%1,%2,%3};"
                 : "+f"(c[0]), "+f"(c[1]), "+f"(c[2]), "+f"(c[3])
                 : "r"(a[0]), "r"(a[1]), "r"(a[2]), "r"(a[3]), "r"(b[0]), "r"(b[1]));
}

// ============================================================================
// HMMA bf16 GEMM with 3-way split: D[m][n] = sum_k A[m][k]*B[n][k] (fp32)
// which==0: logits (A=T2, B=P2, D=g_S, K=256)
// which==1: AV     (A=G2, B=PW2, D=g_Y, K=4096)
// Block: 128x128x32, 8 warps (2x4), warp tile 64x32.
// smem per buffer (u32): Ah[128*20] Al Bh Bl ; row stride 20 u32 (80 B).
// ============================================================================
#define RS 20            // row stride in u32
#define TILE_U32 (128 * RS)          // 2560
#define BUF_U32  (4 * TILE_U32)      // 10240
#define SMEM_MMA_BYTES (2 * BUF_U32 * 4)   // 81920

__global__ void __launch_bounds__(256, 1)
mma_gemm_kernel(int which)
{
    extern __shared__ unsigned su[];
    const unsigned sb = smem_u32(su);
    const int tid = threadIdx.x;
    const int wid = tid >> 5, lane = tid & 31;
    const int warp_m = wid & 1, warp_n = wid >> 1;
    const int m0 = blockIdx.y * 128, n0 = blockIdx.x * 128;
    const int batch = blockIdx.z;

    const unsigned* A; const unsigned* B; float* Dst;
    int K, lda, ldb;
    if (which == 0) {
        A = g_T2 + (size_t)batch * NS * C;
        B = g_P2 + (size_t)batch * NS * C;
        Dst = g_S + (size_t)batch * NS * NS;
        K = C; lda = C; ldb = C;
    } else {
        A = g_G2 + (size_t)batch * C * NS;
        B = g_PW2 + (size_t)batch * NS * NS;
        Dst = g_Y + (size_t)batch * C * NS;
        K = NS; lda = NS; ldb = NS;
    }
    const int ldd = NS;

    // ---- global staging: thread covers row = tid>>1, u32 cols kh*16..+15 ----
    const int grow = tid >> 1;
    const int kh = tid & 1;
    uint4 ra[4], rb[4];

    auto load_regs = [&](int chunk) {
        const uint4* Ar = (const uint4*)&A[(size_t)(m0 + grow) * lda + chunk * 32 + kh * 16];
        const uint4* Br = (const uint4*)&B[(size_t)(n0 + grow) * ldb + chunk * 32 + kh * 16];
        #pragma unroll
        for (int q = 0; q < 4; q++) { ra[q] = Ar[q]; rb[q] = Br[q]; }
    };
    auto store_smem = [&](int buf) {
        unsigned* s = su + buf * BUF_U32;
        const int base = grow * RS + kh * 8;
        #pragma unroll
        for (int q = 0; q < 4; q++) {
            uint4 va = ra[q], vb = rb[q];
            uint2 ah = make_uint2((va.x >> 16) | (va.y & 0xFFFF0000u),
                                  (va.z >> 16) | (va.w & 0xFFFF0000u));
            uint2 al = make_uint2((va.x & 0xFFFFu) | (va.y << 16),
                                  (va.z & 0xFFFFu) | (va.w << 16));
            uint2 bh = make_uint2((vb.x >> 16) | (vb.y & 0xFFFF0000u),
                                  (vb.z >> 16) | (vb.w & 0xFFFF0000u));
            uint2 bl = make_uint2((vb.x & 0xFFFFu) | (vb.y << 16),
                                  (vb.z & 0xFFFFu) | (vb.w << 16));
            int idx = base + q * 2;
            *(uint2*)&s[idx]                = ah;
            *(uint2*)&s[TILE_U32 + idx]     = al;
            *(uint2*)&s[2 * TILE_U32 + idx] = bh;
            *(uint2*)&s[3 * TILE_U32 + idx] = bl;
        }
    };

    float acc[4][4][4] = {};   // [mf][nf][4]

    // ldmatrix per-lane base offsets (u32 idx within a tile)
    const int lrow = lane & 15;
    const int lkoff = (lane >> 4) * 4;

    const int nch = K / 32;
    load_regs(0);
    store_smem(0);
    __syncthreads();

    for (int i = 0; i < nch; i++) {
        int buf = i & 1;
        if (i + 1 < nch) load_regs(i + 1);

        const unsigned tb = sb + (unsigned)buf * (BUF_U32 * 4);
        #pragma unroll
        for (int ks = 0; ks < 2; ks++) {
            const int koff = ks * 8 + lkoff;
            // B fragments: hi & lo, 4 nf
            unsigned bh[4][2], bl[4][2];
            #pragma unroll
            for (int np = 0; np < 2; np++) {
                int brow = warp_n * 32 + np * 16 + lrow;
                unsigned ad = tb + (unsigned)(2 * TILE_U32 + brow * RS + koff) * 4;
                unsigned r0, r1, r2, r3;
                ldsm_x4(ad, r0, r1, r2, r3);
                bh[2*np][0] = r0; bh[2*np+1][0] = r1; bh[2*np][1] = r2; bh[2*np+1][1] = r3;
                ad += (unsigned)TILE_U32 * 4;
                ldsm_x4(ad, r0, r1, r2, r3);
                bl[2*np][0] = r0; bl[2*np+1][0] = r1; bl[2*np][1] = r2; bl[2*np+1][1] = r3;
            }
            #pragma unroll
            for (int mf = 0; mf < 4; mf++) {
                int arow = warp_m * 64 + mf * 16 + lrow;
                unsigned ad = tb + (unsigned)(arow * RS + koff) * 4;
                unsigned ahr[4], alr[4];
                ldsm_x4(ad, ahr[0], ahr[1], ahr[2], ahr[3]);
                ldsm_x4(ad + (unsigned)TILE_U32 * 4, alr[0], alr[1], alr[2], alr[3]);
                #pragma unroll
                for (int nf = 0; nf < 4; nf++) {
                    mma16816(acc[mf][nf], ahr, bh[nf]);   // Ah*Bh
                    mma16816(acc[mf][nf], ahr, bl[nf]);   // Ah*Bl
                    mma16816(acc[mf][nf], alr, bh[nf]);   // Al*Bh
                }
            }
        }
        __syncthreads();
        if (i + 1 < nch) { store_smem(buf ^ 1); __syncthreads(); }
    }

    // ---- epilogue ----
    #pragma unroll
    for (int mf = 0; mf < 4; mf++) {
        int m = m0 + warp_m * 64 + mf * 16 + (lane >> 2);
        #pragma unroll
        for (int nf = 0; nf < 4; nf++) {
            int n = n0 + warp_n * 32 + nf * 8 + (lane & 3) * 2;
            float2 v0 = make_float2(acc[mf][nf][0], acc[mf][nf][1]);
            float2 v1 = make_float2(acc[mf][nf][2], acc[mf][nf][3]);
            *(float2*)&Dst[(size_t)m * ldd + n] = v0;
            *(float2*)&Dst[(size_t)(m + 8) * ldd + n] = v1;
        }
    }
}

// ============================================================================
// SIMT 128x128 GEMM tile (round-2, proven)
// ============================================================================
#define SROW 132
template<int TA, int TB>
__device__ __forceinline__ void gemm_tile(
    const float* __restrict__ A, int lda,
    const float* __restrict__ B, int ldb,
    int K, int m0, int n0, float acc[8][8])
{
    __shared__ float As[16][SROW];
    __shared__ float Bs[16][SROW];
    const int tid = threadIdx.x;
    const int tx = tid & 15, ty = tid >> 4;
    float4 a0, a1, b0, b1;

    auto loadA = [&](int kt) {
        if (TA == 0) {
            int rr = tid >> 4, c = (tid & 15) * 8;
            const float* p = &A[(size_t)(kt + rr) * lda + m0 + c];
            a0 = *(const float4*)p; a1 = *(const float4*)(p + 4);
        } else {
            int m = tid >> 1, k4 = (tid & 1) * 8;
            const float* p = &A[(size_t)(m0 + m) * lda + kt + k4];
            a0 = *(const float4*)p; a1 = *(const float4*)(p + 4);
        }
    };
    auto loadB = [&](int kt) {
        if (TB == 0) {
            int rr = tid >> 4, c = (tid & 15) * 8;
            const float* p = &B[(size_t)(kt + rr) * ldb + n0 + c];
            b0 = *(const float4*)p; b1 = *(const float4*)(p + 4);
        } else {
            int n = tid >> 1, k4 = (tid & 1) * 8;
            const float* p = &B[(size_t)(n0 + n) * ldb + kt + k4];
            b0 = *(const float4*)p; b1 = *(const float4*)(p + 4);
        }
    };
    auto storeA = [&]() {
        if (TA == 0) {
            int rr = tid >> 4, c = (tid & 15) * 8;
            *(float4*)&As[rr][c] = a0; *(float4*)&As[rr][c + 4] = a1;
        } else {
            int m = tid >> 1, k4 = (tid & 1) * 8;
            As[k4+0][m] = a0.x; As[k4+1][m] = a0.y; As[k4+2][m] = a0.z; As[k4+3][m] = a0.w;
            As[k4+4][m] = a1.x; As[k4+5][m] = a1.y; As[k4+6][m] = a1.z; As[k4+7][m] = a1.w;
        }
    };
    auto storeB = [&]() {
        if (TB == 0) {
            int rr = tid >> 4, c = (tid & 15) * 8;
            *(float4*)&Bs[rr][c] = b0; *(float4*)&Bs[rr][c + 4] = b1;
        } else {
            int n = tid >> 1, k4 = (tid & 1) * 8;
            Bs[k4+0][n] = b0.x; Bs[k4+1][n] = b0.y; Bs[k4+2][n] = b0.z; Bs[k4+3][n] = b0.w;
            Bs[k4+4][n] = b1.x; Bs[k4+5][n] = b1.y; Bs[k4+6][n] = b1.z; Bs[k4+7][n] = b1.w;
        }
    };

    loadA(0); loadB(0);
    storeA(); storeB();
    __syncthreads();

    for (int kt = 0; kt < K; kt += 16) {
        bool more = (kt + 16) < K;
        if (more) { loadA(kt + 16); loadB(kt + 16); }
        #pragma unroll
        for (int kk = 0; kk < 16; kk++) {
            float av[8], bv[8];
            *(float4*)&av[0] = *(const float4*)&As[kk][ty * 4];
            *(float4*)&av[4] = *(const float4*)&As[kk][64 + ty * 4];
            *(float4*)&bv[0] = *(const float4*)&Bs[kk][tx * 4];
            *(float4*)&bv[4] = *(const float4*)&Bs[kk][64 + tx * 4];
            #pragma unroll
            for (int i = 0; i < 8; i++)
                #pragma unroll
                for (int j = 0; j < 8; j++)
                    acc[i][j] += av[i] * bv[j];
        }
        __syncthreads();
        if (more) { storeA(); storeB(); __syncthreads(); }
    }
}
#define ACC_M(i) (m0 + ((i) >= 4 ? 64 : 0) + ty * 4 + ((i) & 3))

// ============================================================================
// proj_qp: T2/P2[pos][chan] = split(X^T W^T + b)
// ============================================================================
__global__ void __launch_bounds__(256, 2)
proj_qp_kernel(const float* __restrict__ x,
               const float* __restrict__ Wt, const float* __restrict__ bt,
               const float* __restrict__ Wp, const float* __restrict__ bp)
{
    int z = blockIdx.z;
    int batch = z >> 1, which = z & 1;
    const float* W = which ? Wp : Wt;
    const float* b = which ? bp : bt;
    unsigned* Out = (which ? g_P2 : g_T2) + (size_t)batch * NS * C;
    const float* X = x + (size_t)batch * C * NS;

    int m0 = blockIdx.y * 128, n0 = blockIdx.x * 128;
    int tx = threadIdx.x & 15, ty = threadIdx.x >> 4;
    float acc[8][8] = {};
    gemm_tile<0, 1>(X, NS, W, C, C, m0, n0, acc);

    #pragma unroll
    for (int i = 0; i < 8; i++) {
        int m = ACC_M(i);
        #pragma unroll
        for (int jj = 0; jj < 2; jj++) {
            int n = n0 + jj * 64 + tx * 4;
            uint4 pk;
            pk.x = pack_split(acc[i][jj*4+0] + b[n+0]);
            pk.y = pack_split(acc[i][jj*4+1] + b[n+1]);
            pk.z = pack_split(acc[i][jj*4+2] + b[n+2]);
            pk.w = pack_split(acc[i][jj*4+3] + b[n+3]);
            *(uint4*)&Out[(size_t)m * C + n] = pk;
        }
    }
}

// ============================================================================
// proj_g: G2[chan][pos] = split(W X + b)
// ============================================================================
__global__ void __launch_bounds__(256, 2)
proj_g_kernel(const float* __restrict__ x,
              const float* __restrict__ Wg, const float* __restrict__ bg)
{
    int batch = blockIdx.z;
    unsigned* Out = g_G2 + (size_t)batch * C * NS;
    const float* X = x + (size_t)batch * C * NS;

    int m0 = blockIdx.y * 128, n0 = blockIdx.x * 128;
    int tx = threadIdx.x & 15, ty = threadIdx.x >> 4;
    float acc[8][8] = {};
    gemm_tile<1, 0>(Wg, C, X, NS, C, m0, n0, acc);

    #pragma unroll
    for (int i = 0; i < 8; i++) {
        int m = ACC_M(i);
        float bias = bg[m];
        #pragma unroll
        for (int jj = 0; jj < 2; jj++) {
            int n = n0 + jj * 64 + tx * 4;
            uint4 pk;
            pk.x = pack_split(acc[i][jj*4+0] + bias);
            pk.y = pack_split(acc[i][jj*4+1] + bias);
            pk.z = pack_split(acc[i][jj*4+2] + bias);
            pk.w = pack_split(acc[i][jj*4+3] + bias);
            *(uint4*)&Out[(size_t)m * NS + n] = pk;
        }
    }
}

// ============================================================================
// softmax: fp32 logits row -> packed split weights
// ============================================================================
__global__ void softmax_kernel()
{
    size_t row = blockIdx.x;
    const float* p = g_S + row * (size_t)NS;
    unsigned* po = g_PW2 + row * (size_t)NS;
    int tid = threadIdx.x;
    int lane = tid & 31, wd = tid >> 5;
    __shared__ float red[8];

    float4 v[4];
    float mx = -1e30f;
    #pragma unroll
    for (int i = 0; i < 4; i++) {
        v[i] = *(const float4*)&p[(tid + i * 256) * 4];
        mx = fmaxf(mx, fmaxf(fmaxf(v[i].x, v[i].y), fmaxf(v[i].z, v[i].w)));
    }
    #pragma unroll
    for (int off = 16; off > 0; off >>= 1)
        mx = fmaxf(mx, __shfl_xor_sync(0xffffffffu, mx, off));
    if (lane == 0) red[wd] = mx;
    __syncthreads();
    mx = red[0];
    #pragma unroll
    for (int w = 1; w < 8; w++) mx = fmaxf(mx, red[w]);

    float s = 0.f;
    #pragma unroll
    for (int i = 0; i < 4; i++) {
        v[i].x = expf(v[i].x - mx); v[i].y = expf(v[i].y - mx);
        v[i].z = expf(v[i].z - mx); v[i].w = expf(v[i].w - mx);
        s += v[i].x + v[i].y + v[i].z + v[i].w;
    }
    #pragma unroll
    for (int off = 16; off > 0; off >>= 1)
        s += __shfl_xor_sync(0xffffffffu, s, off);
    __syncthreads();
    if (lane == 0) red[wd] = s;
    __syncthreads();
    s = 0.f;
    #pragma unroll
    for (int w = 0; w < 8; w++) s += red[w];
    float inv = 1.0f / s;

    #pragma unroll
    for (int i = 0; i < 4; i++) {
        uint4 o;
        o.x = pack_split(v[i].x * inv);
        o.y = pack_split(v[i].y * inv);
        o.z = pack_split(v[i].z * inv);
        o.w = pack_split(v[i].w * inv);
        *(uint4*)&po[(tid + i * 256) * 4] = o;
    }
}

// ============================================================================
// out = x + Wo @ Y + bo (SIMT)
// ============================================================================
__global__ void __launch_bounds__(256, 2)
out_kernel(const float* __restrict__ x,
           const float* __restrict__ Wo,
           const float* __restrict__ bo,
           float* __restrict__ out)
{
    int batch = blockIdx.z;
    const float* B = g_Y + (size_t)batch * C * NS;
    const float* Xr = x + (size_t)batch * C * NS;
    float* O = out + (size_t)batch * C * NS;

    int m0 = blockIdx.y * 128, n0 = blockIdx.x * 128;
    int tx = threadIdx.x & 15, ty = threadIdx.x >> 4;
    float acc[8][8] = {};
    gemm_tile<1, 0>(Wo, C, B, NS, C, m0, n0, acc);

    #pragma unroll
    for (int i = 0; i < 8; i++) {
        int m = ACC_M(i);
        float bias = bo[m];
        #pragma unroll
        for (int jj = 0; jj < 2; jj++) {
            int n = n0 + jj * 64 + tx * 4;
            float4 xr = *(const float4*)&Xr[(size_t)m * NS + n];
            float4 rr = {acc[i][jj*4+0] + bias + xr.x, acc[i][jj*4+1] + bias + xr.y,
                         acc[i][jj*4+2] + bias + xr.z, acc[i][jj*4+3] + bias + xr.w};
            *(float4*)&O[(size_t)m * NS + n] = rr;
        }
    }
}

// ============================================================================
extern "C" void kernel_launch(void* const* d_in, const int* in_sizes, int n_in,
                              void* d_out, int out_size)
{
    const float* x  = (const float*)d_in[0];
    const float* Wg = (const float*)d_in[1];
    const float* bg = (const float*)d_in[2];
    const float* Wt = (const float*)d_in[3];
    const float* bt = (const float*)d_in[4];
    const float* Wp = (const float*)d_in[5];
    const float* bp = (const float*)d_in[6];
    const float* Wo = (const float*)d_in[7];
    const float* bo = (const float*)d_in[8];
    float* out = (float*)d_out;

    cudaFuncSetAttribute(mma_gemm_kernel, cudaFuncAttributeMaxDynamicSharedMemorySize,
                         SMEM_MMA_BYTES);

    proj_qp_kernel<<<dim3(C / 128, NS / 128, NB * 2), 256>>>(x, Wt, bt, Wp, bp);
    proj_g_kernel <<<dim3(NS / 128, C / 128, NB),     256>>>(x, Wg, bg);
    mma_gemm_kernel<<<dim3(NS / 128, NS / 128, NB), 256, SMEM_MMA_BYTES>>>(0);  // logits
    softmax_kernel<<<NB * NS, 256>>>();
    mma_gemm_kernel<<<dim3(NS / 128, C / 128, NB), 256, SMEM_MMA_BYTES>>>(1);   // AV
    out_kernel    <<<dim3(NS / 128, C / 128, NB),   256>>>(x, Wo, bo, out);
}

// round 5
// speedup vs baseline: 2.3328x; 1.1780x over previous
#include <cuda_runtime.h>
#include <cuda_bf16.h>
#include <cuda_fp16.h>

#define NB 4
#define C  256
#define NS 4096

// ---- device scratch (allocation-free) ----
__device__ __nv_bfloat16 g_Th[NB * NS * C];    // theta hi [q][c]
__device__ __nv_bfloat16 g_Tl[NB * NS * C];    // theta lo
__device__ __nv_bfloat16 g_Ph[NB * NS * C];    // phi hi  [k'][c]
__device__ __nv_bfloat16 g_Pl[NB * NS * C];    // phi lo
__device__ __half        g_Gh[NB * C * NS];    // g hi [c][k]
__device__ __half        g_Gl[NB * C * NS];    // g lo
__device__ float         g_S [(size_t)NB * NS * NS];   // logits fp32
__device__ __half        g_PWh[(size_t)NB * NS * NS];  // softmax weights fp16
__device__ float         g_Y [NB * C * NS];    // attention out fp32 [c][q]

__device__ __forceinline__ unsigned smem_u32(const void* p) {
    unsigned a;
    asm("{ .reg .u64 t; cvta.to.shared.u64 t, %1; cvt.u32.u64 %0, t; }" : "=r"(a) : "l"(p));
    return a;
}
__device__ __forceinline__ void ldsm_x4(unsigned addr, unsigned& r0, unsigned& r1,
                                        unsigned& r2, unsigned& r3) {
    asm volatile("ldmatrix.sync.aligned.m8n8.x4.shared.b16 {%0,%1,%2,%3}, [%4];"
                 : "=r"(r0), "=r"(r1), "=r"(r2), "=r"(r3) : "r"(addr));
}
__device__ __forceinline__ void mma_bf16(float* c, const unsigned* a, const unsigned* b) {
    asm volatile("mma.sync.aligned.m16n8k16.row.col.f32.bf16.bf16.f32 "
                 "{%0,%1,%2,%3}, {%4,%5,%6,%7}, {%8,%9}, {%0,%1,%2,%3};"
                 : "+f"(c[0]), "+f"(c[1]), "+f"(c[2]), "+f"(c[3])
                 : "r"(a[0]), "r"(a[1]), "r"(a[2]), "r"(a[3]), "r"(b[0]), "r"(b[1]));
}
__device__ __forceinline__ void mma_fp16(float* c, const unsigned* a, const unsigned* b) {
    asm volatile("mma.sync.aligned.m16n8k16.row.col.f32.f16.f16.f32 "
                 "{%0,%1,%2,%3}, {%4,%5,%6,%7}, {%8,%9}, {%0,%1,%2,%3};"
                 : "+f"(c[0]), "+f"(c[1]), "+f"(c[2]), "+f"(c[3])
                 : "r"(a[0]), "r"(a[1]), "r"(a[2]), "r"(a[3]), "r"(b[0]), "r"(b[1]));
}
__device__ __forceinline__ void cp16(unsigned dst, const void* src) {
    asm volatile("cp.async.cg.shared.global [%0], [%1], 16;" :: "r"(dst), "l"(src));
}
#define CP_COMMIT() asm volatile("cp.async.commit_group;" ::: "memory")
#define CP_WAIT(n)  asm volatile("cp.async.wait_group %0;" :: "n"(n) : "memory")

// ============================================================================
// HMMA GEMM, 128x128x32 block tile, 8 warps (2x4), 3-stage cp.async pipeline.
// MODE 0: logits (bf16 3-term: Ah*Bh + Ah*Bl + Al*Bh), K=256
// MODE 1: AV     (fp16 2-term: Ah*B + Al*B),            K=4096
// smem plane: 128 rows x 16 u32 (32 K-elems bf16/fp16), row stride RS=20 u32.
// ============================================================================
#define RS 20
#define TILE_U32 (128 * RS)              // 2560
#define NSTAGE 3

template<int MODE>
__global__ void __launch_bounds__(256, 1)
mma_gemm_kernel()
{
    constexpr int PLANES = (MODE == 0) ? 4 : 3;
    constexpr int STAGE_U32 = PLANES * TILE_U32;

    extern __shared__ unsigned su[];
    const unsigned sb = smem_u32(su);
    const int tid = threadIdx.x;
    const int wid = tid >> 5, lane = tid & 31;
    const int warp_m = wid & 1, warp_n = wid >> 1;
    const int m0 = blockIdx.y * 128, n0 = blockIdx.x * 128;
    const int batch = blockIdx.z;

    const __nv_bfloat16 *pA0, *pA1, *pB0, *pB1;
    float* Dst;
    int K, lda, ldb;
    if (MODE == 0) {
        pA0 = g_Th + (size_t)batch * NS * C;
        pA1 = g_Tl + (size_t)batch * NS * C;
        pB0 = g_Ph + (size_t)batch * NS * C;
        pB1 = g_Pl + (size_t)batch * NS * C;
        Dst = g_S + (size_t)batch * NS * NS;
        K = C; lda = C; ldb = C;
    } else {
        pA0 = (const __nv_bfloat16*)(g_Gh + (size_t)batch * C * NS);
        pA1 = (const __nv_bfloat16*)(g_Gl + (size_t)batch * C * NS);
        pB0 = (const __nv_bfloat16*)(g_PWh + (size_t)batch * NS * NS);
        pB1 = nullptr;
        Dst = g_Y + (size_t)batch * C * NS;
        K = NS; lda = NS; ldb = NS;
    }
    const int ldd = NS;
    const int nch = K / 32;

    // issue cp.async loads for one stage (each thread: 2 x 16B per plane)
    auto issue = [&](int chunk, int buf) {
        const unsigned sbase = sb + (unsigned)buf * (STAGE_U32 * 4);
        const int k0 = chunk * 32;
        #pragma unroll
        for (int c = 0; c < 2; c++) {
            int idx = tid + c * 256;
            int row = idx >> 2, q = idx & 3;
            unsigned doff = (unsigned)(row * RS + q * 4) * 4;
            const __nv_bfloat16* a0 = pA0 + (size_t)(m0 + row) * lda + k0 + q * 8;
            const __nv_bfloat16* a1 = pA1 + (size_t)(m0 + row) * lda + k0 + q * 8;
            const __nv_bfloat16* b0 = pB0 + (size_t)(n0 + row) * ldb + k0 + q * 8;
            cp16(sbase + doff, a0);
            cp16(sbase + (unsigned)(TILE_U32 * 4) + doff, a1);
            cp16(sbase + (unsigned)(2 * TILE_U32 * 4) + doff, b0);
            if (MODE == 0) {
                const __nv_bfloat16* b1 = pB1 + (size_t)(n0 + row) * ldb + k0 + q * 8;
                cp16(sbase + (unsigned)(3 * TILE_U32 * 4) + doff, b1);
            }
        }
    };

    float acc[4][4][4] = {};
    const int lrow = lane & 15;
    const int lkoff = (lane >> 4) * 4;

    issue(0, 0); CP_COMMIT();
    if (nch > 1) { issue(1, 1); CP_COMMIT(); }

    for (int i = 0; i < nch; i++) {
        if (i < nch - 1) { CP_WAIT(1); } else { CP_WAIT(0); }
        __syncthreads();
        if (i + NSTAGE - 1 < nch) { issue(i + NSTAGE - 1, (i + NSTAGE - 1) % NSTAGE); CP_COMMIT(); }

        const unsigned tb = sb + (unsigned)(i % NSTAGE) * (STAGE_U32 * 4);
        #pragma unroll
        for (int ks = 0; ks < 2; ks++) {
            const int koff = ks * 8 + lkoff;
            unsigned bh[4][2], bl[4][2];
            #pragma unroll
            for (int np = 0; np < 2; np++) {
                int brow = warp_n * 32 + np * 16 + lrow;
                unsigned ad = tb + (unsigned)(2 * TILE_U32 + brow * RS + koff) * 4;
                unsigned r0, r1, r2, r3;
                ldsm_x4(ad, r0, r1, r2, r3);
                bh[2*np][0] = r0; bh[2*np+1][0] = r1; bh[2*np][1] = r2; bh[2*np+1][1] = r3;
                if (MODE == 0) {
                    ldsm_x4(ad + (unsigned)TILE_U32 * 4, r0, r1, r2, r3);
                    bl[2*np][0] = r0; bl[2*np+1][0] = r1; bl[2*np][1] = r2; bl[2*np+1][1] = r3;
                }
            }
            #pragma unroll
            for (int mf = 0; mf < 4; mf++) {
                int arow = warp_m * 64 + mf * 16 + lrow;
                unsigned ad = tb + (unsigned)(arow * RS + koff) * 4;
                unsigned ahr[4], alr[4];
                ldsm_x4(ad, ahr[0], ahr[1], ahr[2], ahr[3]);
                ldsm_x4(ad + (unsigned)TILE_U32 * 4, alr[0], alr[1], alr[2], alr[3]);
                #pragma unroll
                for (int nf = 0; nf < 4; nf++) {
                    if (MODE == 0) {
                        mma_bf16(acc[mf][nf], ahr, bh[nf]);
                        mma_bf16(acc[mf][nf], ahr, bl[nf]);
                        mma_bf16(acc[mf][nf], alr, bh[nf]);
                    } else {
                        mma_fp16(acc[mf][nf], ahr, bh[nf]);
                        mma_fp16(acc[mf][nf], alr, bh[nf]);
                    }
                }
            }
        }
        __syncthreads();
    }

    #pragma unroll
    for (int mf = 0; mf < 4; mf++) {
        int m = m0 + warp_m * 64 + mf * 16 + (lane >> 2);
        #pragma unroll
        for (int nf = 0; nf < 4; nf++) {
            int n = n0 + warp_n * 32 + nf * 8 + (lane & 3) * 2;
            *(float2*)&Dst[(size_t)m * ldd + n]       = make_float2(acc[mf][nf][0], acc[mf][nf][1]);
            *(float2*)&Dst[(size_t)(m + 8) * ldd + n] = make_float2(acc[mf][nf][2], acc[mf][nf][3]);
        }
    }
}

// ============================================================================
// SIMT 128x128 GEMM tile (proven)
// ============================================================================
#define SROW 132
template<int TA, int TB>
__device__ __forceinline__ void gemm_tile(
    const float* __restrict__ A, int lda,
    const float* __restrict__ B, int ldb,
    int K, int m0, int n0, float acc[8][8])
{
    __shared__ float As[16][SROW];
    __shared__ float Bs[16][SROW];
    const int tid = threadIdx.x;
    const int tx = tid & 15, ty = tid >> 4;
    float4 a0, a1, b0, b1;

    auto loadA = [&](int kt) {
        if (TA == 0) {
            int rr = tid >> 4, c = (tid & 15) * 8;
            const float* p = &A[(size_t)(kt + rr) * lda + m0 + c];
            a0 = *(const float4*)p; a1 = *(const float4*)(p + 4);
        } else {
            int m = tid >> 1, k4 = (tid & 1) * 8;
            const float* p = &A[(size_t)(m0 + m) * lda + kt + k4];
            a0 = *(const float4*)p; a1 = *(const float4*)(p + 4);
        }
    };
    auto loadB = [&](int kt) {
        if (TB == 0) {
            int rr = tid >> 4, c = (tid & 15) * 8;
            const float* p = &B[(size_t)(kt + rr) * ldb + n0 + c];
            b0 = *(const float4*)p; b1 = *(const float4*)(p + 4);
        } else {
            int n = tid >> 1, k4 = (tid & 1) * 8;
            const float* p = &B[(size_t)(n0 + n) * ldb + kt + k4];
            b0 = *(const float4*)p; b1 = *(const float4*)(p + 4);
        }
    };
    auto storeA = [&]() {
        if (TA == 0) {
            int rr = tid >> 4, c = (tid & 15) * 8;
            *(float4*)&As[rr][c] = a0; *(float4*)&As[rr][c + 4] = a1;
        } else {
            int m = tid >> 1, k4 = (tid & 1) * 8;
            As[k4+0][m] = a0.x; As[k4+1][m] = a0.y; As[k4+2][m] = a0.z; As[k4+3][m] = a0.w;
            As[k4+4][m] = a1.x; As[k4+5][m] = a1.y; As[k4+6][m] = a1.z; As[k4+7][m] = a1.w;
        }
    };
    auto storeB = [&]() {
        if (TB == 0) {
            int rr = tid >> 4, c = (tid & 15) * 8;
            *(float4*)&Bs[rr][c] = b0; *(float4*)&Bs[rr][c + 4] = b1;
        } else {
            int n = tid >> 1, k4 = (tid & 1) * 8;
            Bs[k4+0][n] = b0.x; Bs[k4+1][n] = b0.y; Bs[k4+2][n] = b0.z; Bs[k4+3][n] = b0.w;
            Bs[k4+4][n] = b1.x; Bs[k4+5][n] = b1.y; Bs[k4+6][n] = b1.z; Bs[k4+7][n] = b1.w;
        }
    };

    loadA(0); loadB(0);
    storeA(); storeB();
    __syncthreads();

    for (int kt = 0; kt < K; kt += 16) {
        bool more = (kt + 16) < K;
        if (more) { loadA(kt + 16); loadB(kt + 16); }
        #pragma unroll
        for (int kk = 0; kk < 16; kk++) {
            float av[8], bv[8];
            *(float4*)&av[0] = *(const float4*)&As[kk][ty * 4];
            *(float4*)&av[4] = *(const float4*)&As[kk][64 + ty * 4];
            *(float4*)&bv[0] = *(const float4*)&Bs[kk][tx * 4];
            *(float4*)&bv[4] = *(const float4*)&Bs[kk][64 + tx * 4];
            #pragma unroll
            for (int i = 0; i < 8; i++)
                #pragma unroll
                for (int j = 0; j < 8; j++)
                    acc[i][j] += av[i] * bv[j];
        }
        __syncthreads();
        if (more) { storeA(); storeB(); __syncthreads(); }
    }
}
#define ACC_M(i) (m0 + ((i) >= 4 ? 64 : 0) + ty * 4 + ((i) & 3))

__device__ __forceinline__ unsigned short bfu(__nv_bfloat16 h) { return __bfloat16_as_ushort(h); }

// ============================================================================
// proj_qp: T/P planes [q][c] = split_bf16(X^T W^T + b)
// ============================================================================
__global__ void __launch_bounds__(256, 2)
proj_qp_kernel(const float* __restrict__ x,
               const float* __restrict__ Wt, const float* __restrict__ bt,
               const float* __restrict__ Wp, const float* __restrict__ bp)
{
    int z = blockIdx.z;
    int batch = z >> 1, which = z & 1;
    const float* W = which ? Wp : Wt;
    const float* b = which ? bp : bt;
    __nv_bfloat16* Oh = (which ? g_Ph : g_Th) + (size_t)batch * NS * C;
    __nv_bfloat16* Ol = (which ? g_Pl : g_Tl) + (size_t)batch * NS * C;
    const float* X = x + (size_t)batch * C * NS;

    int m0 = blockIdx.y * 128, n0 = blockIdx.x * 128;
    int tx = threadIdx.x & 15, ty = threadIdx.x >> 4;
    float acc[8][8] = {};
    gemm_tile<0, 1>(X, NS, W, C, C, m0, n0, acc);

    #pragma unroll
    for (int i = 0; i < 8; i++) {
        int m = ACC_M(i);
        #pragma unroll
        for (int jj = 0; jj < 2; jj++) {
            int n = n0 + jj * 64 + tx * 4;
            unsigned h[4], l[4];
            #pragma unroll
            for (int q = 0; q < 4; q++) {
                float v = acc[i][jj*4+q] + b[n+q];
                __nv_bfloat16 hb = __float2bfloat16(v);
                __nv_bfloat16 lb = __float2bfloat16(v - __bfloat162float(hb));
                h[q] = bfu(hb); l[q] = bfu(lb);
            }
            uint2 ph = make_uint2(h[0] | (h[1] << 16), h[2] | (h[3] << 16));
            uint2 pl = make_uint2(l[0] | (l[1] << 16), l[2] | (l[3] << 16));
            *(uint2*)&Oh[(size_t)m * C + n] = ph;
            *(uint2*)&Ol[(size_t)m * C + n] = pl;
        }
    }
}

// ============================================================================
// proj_g: G planes [c][k] = split_fp16(W X + b)
// ============================================================================
__global__ void __launch_bounds__(256, 2)
proj_g_kernel(const float* __restrict__ x,
              const float* __restrict__ Wg, const float* __restrict__ bg)
{
    int batch = blockIdx.z;
    __half* Oh = g_Gh + (size_t)batch * C * NS;
    __half* Ol = g_Gl + (size_t)batch * C * NS;
    const float* X = x + (size_t)batch * C * NS;

    int m0 = blockIdx.y * 128, n0 = blockIdx.x * 128;
    int tx = threadIdx.x & 15, ty = threadIdx.x >> 4;
    float acc[8][8] = {};
    gemm_tile<1, 0>(Wg, C, X, NS, C, m0, n0, acc);

    #pragma unroll
    for (int i = 0; i < 8; i++) {
        int m = ACC_M(i);
        float bias = bg[m];
        #pragma unroll
        for (int jj = 0; jj < 2; jj++) {
            int n = n0 + jj * 64 + tx * 4;
            unsigned h[4], l[4];
            #pragma unroll
            for (int q = 0; q < 4; q++) {
                float v = acc[i][jj*4+q] + bias;
                __half hb = __float2half_rn(v);
                __half lb = __float2half_rn(v - __half2float(hb));
                h[q] = __half_as_ushort(hb); l[q] = __half_as_ushort(lb);
            }
            uint2 ph = make_uint2(h[0] | (h[1] << 16), h[2] | (h[3] << 16));
            uint2 pl = make_uint2(l[0] | (l[1] << 16), l[2] | (l[3] << 16));
            *(uint2*)&Oh[(size_t)m * NS + n] = ph;
            *(uint2*)&Ol[(size_t)m * NS + n] = pl;
        }
    }
}

// ============================================================================
// softmax: fp32 logits -> fp16 weights
// ============================================================================
__global__ void softmax_kernel()
{
    size_t row = blockIdx.x;
    const float* p = g_S + row * (size_t)NS;
    __half* po = g_PWh + row * (size_t)NS;
    int tid = threadIdx.x;
    int lane = tid & 31, wd = tid >> 5;
    __shared__ float red[8];

    float4 v[4];
    float mx = -1e30f;
    #pragma unroll
    for (int i = 0; i < 4; i++) {
        v[i] = *(const float4*)&p[(tid + i * 256) * 4];
        mx = fmaxf(mx, fmaxf(fmaxf(v[i].x, v[i].y), fmaxf(v[i].z, v[i].w)));
    }
    #pragma unroll
    for (int off = 16; off > 0; off >>= 1)
        mx = fmaxf(mx, __shfl_xor_sync(0xffffffffu, mx, off));
    if (lane == 0) red[wd] = mx;
    __syncthreads();
    mx = red[0];
    #pragma unroll
    for (int w = 1; w < 8; w++) mx = fmaxf(mx, red[w]);

    float s = 0.f;
    #pragma unroll
    for (int i = 0; i < 4; i++) {
        v[i].x = expf(v[i].x - mx); v[i].y = expf(v[i].y - mx);
        v[i].z = expf(v[i].z - mx); v[i].w = expf(v[i].w - mx);
        s += v[i].x + v[i].y + v[i].z + v[i].w;
    }
    #pragma unroll
    for (int off = 16; off > 0; off >>= 1)
        s += __shfl_xor_sync(0xffffffffu, s, off);
    __syncthreads();
    if (lane == 0) red[wd] = s;
    __syncthreads();
    s = 0.f;
    #pragma unroll
    for (int w = 0; w < 8; w++) s += red[w];
    float inv = 1.0f / s;

    #pragma unroll
    for (int i = 0; i < 4; i++) {
        __half2 h01 = __floats2half2_rn(v[i].x * inv, v[i].y * inv);
        __half2 h23 = __floats2half2_rn(v[i].z * inv, v[i].w * inv);
        uint2 o = make_uint2(*(unsigned*)&h01, *(unsigned*)&h23);
        *(uint2*)&po[(tid + i * 256) * 4] = o;
    }
}

// ============================================================================
// out = x + Wo @ Y + bo (SIMT)
// ============================================================================
__global__ void __launch_bounds__(256, 2)
out_kernel(const float* __restrict__ x,
           const float* __restrict__ Wo,
           const float* __restrict__ bo,
           float* __restrict__ out)
{
    int batch = blockIdx.z;
    const float* B = g_Y + (size_t)batch * C * NS;
    const float* Xr = x + (size_t)batch * C * NS;
    float* O = out + (size_t)batch * C * NS;

    int m0 = blockIdx.y * 128, n0 = blockIdx.x * 128;
    int tx = threadIdx.x & 15, ty = threadIdx.x >> 4;
    float acc[8][8] = {};
    gemm_tile<1, 0>(Wo, C, B, NS, C, m0, n0, acc);

    #pragma unroll
    for (int i = 0; i < 8; i++) {
        int m = ACC_M(i);
        float bias = bo[m];
        #pragma unroll
        for (int jj = 0; jj < 2; jj++) {
            int n = n0 + jj * 64 + tx * 4;
            float4 xr = *(const float4*)&Xr[(size_t)m * NS + n];
            float4 rr = {acc[i][jj*4+0] + bias + xr.x, acc[i][jj*4+1] + bias + xr.y,
                         acc[i][jj*4+2] + bias + xr.z, acc[i][jj*4+3] + bias + xr.w};
            *(float4*)&O[(size_t)m * NS + n] = rr;
        }
    }
}

// ============================================================================
extern "C" void kernel_launch(void* const* d_in, const int* in_sizes, int n_in,
                              void* d_out, int out_size)
{
    const float* x  = (const float*)d_in[0];
    const float* Wg = (const float*)d_in[1];
    const float* bg = (const float*)d_in[2];
    const float* Wt = (const float*)d_in[3];
    const float* bt = (const float*)d_in[4];
    const float* Wp = (const float*)d_in[5];
    const float* bp = (const float*)d_in[6];
    const float* Wo = (const float*)d_in[7];
    const float* bo = (const float*)d_in[8];
    float* out = (float*)d_out;

    const int SMEM0 = NSTAGE * 4 * TILE_U32 * 4;   // 122880 B (logits)
    const int SMEM1 = NSTAGE * 3 * TILE_U32 * 4;   // 92160 B  (AV)
    cudaFuncSetAttribute(mma_gemm_kernel<0>, cudaFuncAttributeMaxDynamicSharedMemorySize, SMEM0);
    cudaFuncSetAttribute(mma_gemm_kernel<1>, cudaFuncAttributeMaxDynamicSharedMemorySize, SMEM1);

    proj_qp_kernel<<<dim3(C / 128, NS / 128, NB * 2), 256>>>(x, Wt, bt, Wp, bp);
    proj_g_kernel <<<dim3(NS / 128, C / 128, NB),     256>>>(x, Wg, bg);
    mma_gemm_kernel<0><<<dim3(NS / 128, NS / 128, NB), 256, SMEM0>>>();   // logits
    softmax_kernel<<<NB * NS, 256>>>();
    mma_gemm_kernel<1><<<dim3(NS / 128, C / 128, NB), 256, SMEM1>>>();    // AV
    out_kernel    <<<dim3(NS / 128, C / 128, NB),   256>>>(x, Wo, bo, out);
}

// round 7
// speedup vs baseline: 2.8691x; 1.2299x over previous
#include <cuda_runtime.h>
#include <cuda_fp16.h>

#define NB 4
#define C  256
#define NS 4096

// ---- device scratch (allocation-free) ----
__device__ __half g_XTh[NB * NS * C];   // x^T hi  [b][q][c]
__device__ __half g_XTl[NB * NS * C];   // x^T lo
__device__ __half g_Wh[4 * C * C];      // weights hi: Wt,Wp,Wg,Wo
__device__ __half g_Wl[4 * C * C];
__device__ __half g_Th[NB * NS * C];    // theta hi [q][c]
__device__ __half g_Tl[NB * NS * C];
__device__ __half g_Ph[NB * NS * C];    // phi hi [k'][c]
__device__ __half g_Pl[NB * NS * C];
__device__ __half g_Gh[NB * C * NS];    // g fp16 [c][q] (single plane)
__device__ float  g_S [(size_t)NB * NS * NS];   // logits fp32
__device__ __half g_PWh[(size_t)NB * NS * NS];  // softmax weights fp16
__device__ __half g_YTh[NB * NS * C];   // Y^T hi [q][c]
__device__ __half g_YTl[NB * NS * C];

__device__ __forceinline__ unsigned smem_u32(const void* p) {
    unsigned a;
    asm("{ .reg .u64 t; cvta.to.shared.u64 t, %1; cvt.u32.u64 %0, t; }" : "=r"(a) : "l"(p));
    return a;
}
__device__ __forceinline__ void ldsm_x4(unsigned addr, unsigned& r0, unsigned& r1,
                                        unsigned& r2, unsigned& r3) {
    asm volatile("ldmatrix.sync.aligned.m8n8.x4.shared.b16 {%0,%1,%2,%3}, [%4];"
                 : "=r"(r0), "=r"(r1), "=r"(r2), "=r"(r3) : "r"(addr));
}
__device__ __forceinline__ void mma_fp16(float* c, const unsigned* a, const unsigned* b) {
    asm volatile("mma.sync.aligned.m16n8k16.row.col.f32.f16.f16.f32 "
                 "{%0,%1,%2,%3}, {%4,%5,%6,%7}, {%8,%9}, {%0,%1,%2,%3};"
                 : "+f"(c[0]), "+f"(c[1]), "+f"(c[2]), "+f"(c[3])
                 : "r"(a[0]), "r"(a[1]), "r"(a[2]), "r"(a[3]), "r"(b[0]), "r"(b[1]));
}
__device__ __forceinline__ void cp16(unsigned dst, const void* src) {
    asm volatile("cp.async.cg.shared.global [%0], [%1], 16;" :: "r"(dst), "l"(src));
}
#define CP_COMMIT() asm volatile("cp.async.commit_group;" ::: "memory")
#define CP_WAIT(n)  asm volatile("cp.async.wait_group %0;" :: "n"(n) : "memory")

// fp16 hi/lo split of two floats, packed for half2 plane stores
__device__ __forceinline__ uint2 split2(float v0, float v1) {
    __half h0 = __float2half_rn(v0), h1 = __float2half_rn(v1);
    __half l0 = __float2half_rn(v0 - __half2float(h0));
    __half l1 = __float2half_rn(v1 - __half2float(h1));
    __half2 hh = __halves2half2(h0, h1), ll = __halves2half2(l0, l1);
    return make_uint2(*(unsigned*)&hh, *(unsigned*)&ll);
}

// ============================================================================
// Unified HMMA fp16 GEMM: D[m][n] = sum_k A[m][k] * B[n][k]  (fp32 acc)
// CFG 0: proj T/P  A=XT(2 planes) B=W(2)  K=C  -> fp16 split T/P [q][c] (+bias n)
// CFG 1: proj G    A=Wg(2)        B=XT(2) K=C  -> fp16 G [c][q]         (+bias m)
// CFG 2: logits    A=T(2)         B=P(2)  K=C  -> fp32 g_S
// CFG 3: AV        A=PW(1)        B=G(1)  K=NS -> fp16 split Y^T [q][c]
// CFG 4: out       A=Wo(2)        B=YT(2) K=C  -> fp32 d_out (+bias m, +residual)
// 128x128x32 block tile, 8 warps (2x4), 3-stage cp.async pipeline.
// ============================================================================
#define RS 20
#define TILE_U32 (128 * RS)
#define NSTAGE 3

template<int CFG>
__global__ void __launch_bounds__(256, 1)
mma_k(const float* __restrict__ b1, const float* __restrict__ b2,
      const float* __restrict__ xres, float* __restrict__ outp)
{
    constexpr int nA = (CFG == 3) ? 1 : 2;
    constexpr int nB = (CFG == 3) ? 1 : 2;
    constexpr int PLANES = nA + nB;
    constexpr int STAGE_U32 = PLANES * TILE_U32;
    const int K = (CFG == 3) ? NS : C;

    extern __shared__ unsigned su[];
    const unsigned sb = smem_u32(su);
    const int tid = threadIdx.x;
    const int wid = tid >> 5, lane = tid & 31;
    const int warp_m = wid & 1, warp_n = wid >> 1;
    const int m0 = blockIdx.y * 128, n0 = blockIdx.x * 128;

    const __half* Ap[2] = {nullptr, nullptr};
    const __half* Bp[2] = {nullptr, nullptr};
    int lda = C, ldb = C, batch = blockIdx.z, which = 0;

    if (CFG == 0) {
        int z = blockIdx.z; batch = z >> 1; which = z & 1;
        Ap[0] = g_XTh + (size_t)batch * NS * C;  Ap[1] = g_XTl + (size_t)batch * NS * C;
        Bp[0] = g_Wh + (size_t)which * C * C;    Bp[1] = g_Wl + (size_t)which * C * C;
    } else if (CFG == 1) {
        Ap[0] = g_Wh + 2 * C * C;  Ap[1] = g_Wl + 2 * C * C;
        Bp[0] = g_XTh + (size_t)batch * NS * C;  Bp[1] = g_XTl + (size_t)batch * NS * C;
    } else if (CFG == 2) {
        Ap[0] = g_Th + (size_t)batch * NS * C;   Ap[1] = g_Tl + (size_t)batch * NS * C;
        Bp[0] = g_Ph + (size_t)batch * NS * C;   Bp[1] = g_Pl + (size_t)batch * NS * C;
    } else if (CFG == 3) {
        Ap[0] = g_PWh + (size_t)batch * NS * NS; lda = NS;
        Bp[0] = g_Gh + (size_t)batch * C * NS;   ldb = NS;
    } else {
        Ap[0] = g_Wh + 3 * C * C;  Ap[1] = g_Wl + 3 * C * C;
        Bp[0] = g_YTh + (size_t)batch * NS * C;  Bp[1] = g_YTl + (size_t)batch * NS * C;
    }

    auto issue = [&](int chunk, int buf) {
        const unsigned sbase = sb + (unsigned)buf * (STAGE_U32 * 4);
        const int k0 = chunk * 32;
        #pragma unroll
        for (int c = 0; c < 2; c++) {
            int idx = tid + c * 256;
            int row = idx >> 2, q = idx & 3;
            unsigned doff = (unsigned)(row * RS + q * 4) * 4;
            #pragma unroll
            for (int p = 0; p < nA; p++)
                cp16(sbase + (unsigned)(p * TILE_U32 * 4) + doff,
                     Ap[p] + (size_t)(m0 + row) * lda + k0 + q * 8);
            #pragma unroll
            for (int p = 0; p < nB; p++)
                cp16(sbase + (unsigned)((nA + p) * TILE_U32 * 4) + doff,
                     Bp[p] + (size_t)(n0 + row) * ldb + k0 + q * 8);
        }
    };

    float acc[4][4][4] = {};
    const int lrow = lane & 15;
    const int lkoff = (lane >> 4) * 4;
    const int nch = K / 32;

    issue(0, 0); CP_COMMIT();
    if (nch > 1) { issue(1, 1); CP_COMMIT(); }

    for (int i = 0; i < nch; i++) {
        if (i < nch - 1) { CP_WAIT(1); } else { CP_WAIT(0); }
        __syncthreads();
        if (i + NSTAGE - 1 < nch) { issue(i + NSTAGE - 1, (i + NSTAGE - 1) % NSTAGE); CP_COMMIT(); }

        const unsigned tb = sb + (unsigned)(i % NSTAGE) * (STAGE_U32 * 4);
        #pragma unroll
        for (int ks = 0; ks < 2; ks++) {
            const int koff = ks * 8 + lkoff;
            unsigned bfr[nB][4][2];
            #pragma unroll
            for (int pb = 0; pb < nB; pb++) {
                #pragma unroll
                for (int np = 0; np < 2; np++) {
                    int brow = warp_n * 32 + np * 16 + lrow;
                    unsigned ad = tb + (unsigned)((nA + pb) * TILE_U32 + brow * RS + koff) * 4;
                    unsigned r0, r1, r2, r3;
                    ldsm_x4(ad, r0, r1, r2, r3);
                    bfr[pb][2*np][0] = r0; bfr[pb][2*np+1][0] = r1;
                    bfr[pb][2*np][1] = r2; bfr[pb][2*np+1][1] = r3;
                }
            }
            #pragma unroll
            for (int mf = 0; mf < 4; mf++) {
                int arow = warp_m * 64 + mf * 16 + lrow;
                unsigned afr[nA][4];
                #pragma unroll
                for (int pa = 0; pa < nA; pa++) {
                    unsigned ad = tb + (unsigned)(pa * TILE_U32 + arow * RS + koff) * 4;
                    ldsm_x4(ad, afr[pa][0], afr[pa][1], afr[pa][2], afr[pa][3]);
                }
                #pragma unroll
                for (int nf = 0; nf < 4; nf++) {
                    mma_fp16(acc[mf][nf], afr[0], bfr[0][nf]);
                    if (nA == 2 && nB == 2) {
                        mma_fp16(acc[mf][nf], afr[0], bfr[1][nf]);
                        mma_fp16(acc[mf][nf], afr[1], bfr[0][nf]);
                    }
                }
            }
        }
        __syncthreads();
    }

    // ---- epilogue ----
    #pragma unroll
    for (int mf = 0; mf < 4; mf++) {
        int mb = m0 + warp_m * 64 + mf * 16 + (lane >> 2);
        #pragma unroll
        for (int nf = 0; nf < 4; nf++) {
            int n = n0 + warp_n * 32 + nf * 8 + (lane & 3) * 2;
            float* a4 = acc[mf][nf];
            if (CFG == 2) {
                float* D = g_S + (size_t)batch * NS * NS;
                *(float2*)&D[(size_t)mb * NS + n]       = make_float2(a4[0], a4[1]);
                *(float2*)&D[(size_t)(mb + 8) * NS + n] = make_float2(a4[2], a4[3]);
            } else if (CFG == 4) {
                float* D = outp + (size_t)batch * C * NS;
                const float* X = xres + (size_t)batch * C * NS;
                float bi0 = b1[mb], bi1 = b1[mb + 8];
                float2 x0 = *(const float2*)&X[(size_t)mb * NS + n];
                float2 x1 = *(const float2*)&X[(size_t)(mb + 8) * NS + n];
                *(float2*)&D[(size_t)mb * NS + n]       = make_float2(a4[0] + bi0 + x0.x, a4[1] + bi0 + x0.y);
                *(float2*)&D[(size_t)(mb + 8) * NS + n] = make_float2(a4[2] + bi1 + x1.x, a4[3] + bi1 + x1.y);
            } else if (CFG == 0) {
                __half* Oh = (which ? g_Ph : g_Th) + (size_t)batch * NS * C;
                __half* Ol = (which ? g_Pl : g_Tl) + (size_t)batch * NS * C;
                const float* bb = which ? b2 : b1;
                float bn0 = bb[n], bn1 = bb[n + 1];
                uint2 s0 = split2(a4[0] + bn0, a4[1] + bn1);
                uint2 s1 = split2(a4[2] + bn0, a4[3] + bn1);
                *(unsigned*)&Oh[(size_t)mb * C + n]       = s0.x;
                *(unsigned*)&Ol[(size_t)mb * C + n]       = s0.y;
                *(unsigned*)&Oh[(size_t)(mb + 8) * C + n] = s1.x;
                *(unsigned*)&Ol[(size_t)(mb + 8) * C + n] = s1.y;
            } else if (CFG == 1) {
                __half* O = g_Gh + (size_t)batch * C * NS;
                float bi0 = b1[mb], bi1 = b1[mb + 8];
                __half2 h0 = __floats2half2_rn(a4[0] + bi0, a4[1] + bi0);
                __half2 h1 = __floats2half2_rn(a4[2] + bi1, a4[3] + bi1);
                *(unsigned*)&O[(size_t)mb * NS + n]       = *(unsigned*)&h0;
                *(unsigned*)&O[(size_t)(mb + 8) * NS + n] = *(unsigned*)&h1;
            } else {   // CFG 3: Y^T fp16 split
                uint2 s0 = split2(a4[0], a4[1]);
                uint2 s1 = split2(a4[2], a4[3]);
                __half* Oh = g_YTh + (size_t)batch * NS * C;
                __half* Ol = g_YTl + (size_t)batch * NS * C;
                *(unsigned*)&Oh[(size_t)mb * C + n]       = s0.x;
                *(unsigned*)&Ol[(size_t)mb * C + n]       = s0.y;
                *(unsigned*)&Oh[(size_t)(mb + 8) * C + n] = s1.x;
                *(unsigned*)&Ol[(size_t)(mb + 8) * C + n] = s1.y;
            }
        }
    }
}

// ============================================================================
// x^T split: x [b][c][q] fp32 -> XTh/XTl [b][q][c] fp16. 64x64 smem tiles.
// Row stride 68 floats (multiple of 4 -> float4-aligned rows).
// ============================================================================
__global__ void xt_split_kernel(const float* __restrict__ x)
{
    __shared__ float tile[64][68];
    int q0 = blockIdx.x * 64, c0 = blockIdx.y * 64, b = blockIdx.z;
    int tid = threadIdx.x;
    const float* X = x + (size_t)b * C * NS;

    #pragma unroll
    for (int i = 0; i < 4; i++) {
        int c = (tid >> 4) + i * 16;
        int qq = (tid & 15) * 4;
        float4 v = *(const float4*)&X[(size_t)(c0 + c) * NS + q0 + qq];
        tile[qq + 0][c] = v.x; tile[qq + 1][c] = v.y;
        tile[qq + 2][c] = v.z; tile[qq + 3][c] = v.w;
    }
    __syncthreads();

    __half* Oh = g_XTh + (size_t)b * NS * C;
    __half* Ol = g_XTl + (size_t)b * NS * C;
    #pragma unroll
    for (int i = 0; i < 4; i++) {
        int q = (tid >> 4) + i * 16;
        int cc = (tid & 15) * 4;
        float4 v = *(const float4*)&tile[q][cc];
        uint2 s0 = split2(v.x, v.y);
        uint2 s1 = split2(v.z, v.w);
        size_t off = (size_t)(q0 + q) * C + c0 + cc;
        *(uint2*)&Oh[off] = make_uint2(s0.x, s1.x);
        *(uint2*)&Ol[off] = make_uint2(s0.y, s1.y);
    }
}

// ============================================================================
// weight split: Wt,Wp,Wg,Wo fp32 -> g_Wh/g_Wl fp16 planes
// 4 * 65536 elems = 131072 pairs -> 512 blocks x 256 threads
// ============================================================================
__global__ void wsplit_kernel(const float* __restrict__ Wt, const float* __restrict__ Wp,
                              const float* __restrict__ Wg, const float* __restrict__ Wo)
{
    int id = blockIdx.x * 256 + threadIdx.x;      // 0 .. 131071
    int mat = id >> 15;                            // 32768 pairs per matrix
    int off = (id & 32767) * 2;
    const float* W = (mat == 0) ? Wt : (mat == 1) ? Wp : (mat == 2) ? Wg : Wo;
    float2 v = *(const float2*)&W[off];
    uint2 s = split2(v.x, v.y);
    *(unsigned*)&g_Wh[mat * C * C + off] = s.x;
    *(unsigned*)&g_Wl[mat * C * C + off] = s.y;
}

// ============================================================================
// softmax: fp32 logits -> fp16 weights
// ============================================================================
__global__ void softmax_kernel()
{
    size_t row = blockIdx.x;
    const float* p = g_S + row * (size_t)NS;
    __half* po = g_PWh + row * (size_t)NS;
    int tid = threadIdx.x;
    int lane = tid & 31, wd = tid >> 5;
    __shared__ float red[8];

    float4 v[4];
    float mx = -1e30f;
    #pragma unroll
    for (int i = 0; i < 4; i++) {
        v[i] = *(const float4*)&p[(tid + i * 256) * 4];
        mx = fmaxf(mx, fmaxf(fmaxf(v[i].x, v[i].y), fmaxf(v[i].z, v[i].w)));
    }
    #pragma unroll
    for (int off = 16; off > 0; off >>= 1)
        mx = fmaxf(mx, __shfl_xor_sync(0xffffffffu, mx, off));
    if (lane == 0) red[wd] = mx;
    __syncthreads();
    mx = red[0];
    #pragma unroll
    for (int w = 1; w < 8; w++) mx = fmaxf(mx, red[w]);

    float s = 0.f;
    #pragma unroll
    for (int i = 0; i < 4; i++) {
        v[i].x = expf(v[i].x - mx); v[i].y = expf(v[i].y - mx);
        v[i].z = expf(v[i].z - mx); v[i].w = expf(v[i].w - mx);
        s += v[i].x + v[i].y + v[i].z + v[i].w;
    }
    #pragma unroll
    for (int off = 16; off > 0; off >>= 1)
        s += __shfl_xor_sync(0xffffffffu, s, off);
    __syncthreads();
    if (lane == 0) red[wd] = s;
    __syncthreads();
    s = 0.f;
    #pragma unroll
    for (int w = 0; w < 8; w++) s += red[w];
    float inv = 1.0f / s;

    #pragma unroll
    for (int i = 0; i < 4; i++) {
        __half2 h01 = __floats2half2_rn(v[i].x * inv, v[i].y * inv);
        __half2 h23 = __floats2half2_rn(v[i].z * inv, v[i].w * inv);
        uint2 o = make_uint2(*(unsigned*)&h01, *(unsigned*)&h23);
        *(uint2*)&po[(tid + i * 256) * 4] = o;
    }
}

// ============================================================================
extern "C" void kernel_launch(void* const* d_in, const int* in_sizes, int n_in,
                              void* d_out, int out_size)
{
    const float* x  = (const float*)d_in[0];
    const float* Wg = (const float*)d_in[1];
    const float* bg = (const float*)d_in[2];
    const float* Wt = (const float*)d_in[3];
    const float* bt = (const float*)d_in[4];
    const float* Wp = (const float*)d_in[5];
    const float* bp = (const float*)d_in[6];
    const float* Wo = (const float*)d_in[7];
    const float* bo = (const float*)d_in[8];
    float* out = (float*)d_out;

    const int S4 = NSTAGE * 4 * TILE_U32 * 4;   // 122880 (4-plane CFGs)
    const int S2 = NSTAGE * 2 * TILE_U32 * 4;   // 61440  (AV)
    cudaFuncSetAttribute(mma_k<0>, cudaFuncAttributeMaxDynamicSharedMemorySize, S4);
    cudaFuncSetAttribute(mma_k<1>, cudaFuncAttributeMaxDynamicSharedMemorySize, S4);
    cudaFuncSetAttribute(mma_k<2>, cudaFuncAttributeMaxDynamicSharedMemorySize, S4);
    cudaFuncSetAttribute(mma_k<3>, cudaFuncAttributeMaxDynamicSharedMemorySize, S2);
    cudaFuncSetAttribute(mma_k<4>, cudaFuncAttributeMaxDynamicSharedMemorySize, S4);

    wsplit_kernel  <<<512, 256>>>(Wt, Wp, Wg, Wo);
    xt_split_kernel<<<dim3(NS / 64, C / 64, NB), 256>>>(x);

    mma_k<0><<<dim3(C / 128, NS / 128, NB * 2), 256, S4>>>(bt, bp, nullptr, nullptr);       // T,P
    mma_k<1><<<dim3(NS / 128, C / 128, NB),     256, S4>>>(bg, nullptr, nullptr, nullptr);  // G
    mma_k<2><<<dim3(NS / 128, NS / 128, NB),    256, S4>>>(nullptr, nullptr, nullptr, nullptr); // logits
    softmax_kernel<<<NB * NS, 256>>>();
    mma_k<3><<<dim3(C / 128, NS / 128, NB),     256, S2>>>(nullptr, nullptr, nullptr, nullptr); // AV -> Y^T
    mma_k<4><<<dim3(NS / 128, C / 128, NB),     256, S4>>>(bo, nullptr, x, out);            // out
}

// round 8
// speedup vs baseline: 3.2545x; 1.1343x over previous
#include <cuda_runtime.h>
#include <cuda_fp16.h>

#define NB 4
#define C  256
#define NS 4096

// ---- device scratch (allocation-free) ----
__device__ __half g_XTh[NB * NS * C];   // x^T hi  [b][q][c]
__device__ __half g_XTl[NB * NS * C];   // x^T lo
__device__ __half g_Wh[4 * C * C];      // weights hi: Wt,Wp,Wg,Wo
__device__ __half g_Wl[4 * C * C];
__device__ __half g_Th[NB * NS * C];    // theta hi [q][c]
__device__ __half g_Tl[NB * NS * C];
__device__ __half g_Ph[NB * NS * C];    // phi hi [k'][c]
__device__ __half g_Pl[NB * NS * C];
__device__ __half g_Gh[NB * C * NS];    // g fp16 [c][q] (single plane)
__device__ float  g_S [(size_t)NB * NS * NS];   // logits fp32
__device__ __half g_PWh[(size_t)NB * NS * NS];  // softmax weights fp16
__device__ __half g_YTh[NB * NS * C];   // Y^T hi [q][c]
__device__ __half g_YTl[NB * NS * C];

__device__ __forceinline__ unsigned smem_u32(const void* p) {
    unsigned a;
    asm("{ .reg .u64 t; cvta.to.shared.u64 t, %1; cvt.u32.u64 %0, t; }" : "=r"(a) : "l"(p));
    return a;
}
__device__ __forceinline__ void ldsm_x4(unsigned addr, unsigned& r0, unsigned& r1,
                                        unsigned& r2, unsigned& r3) {
    asm volatile("ldmatrix.sync.aligned.m8n8.x4.shared.b16 {%0,%1,%2,%3}, [%4];"
                 : "=r"(r0), "=r"(r1), "=r"(r2), "=r"(r3) : "r"(addr));
}
__device__ __forceinline__ void mma_fp16(float* c, const unsigned* a, const unsigned* b) {
    asm volatile("mma.sync.aligned.m16n8k16.row.col.f32.f16.f16.f32 "
                 "{%0,%1,%2,%3}, {%4,%5,%6,%7}, {%8,%9}, {%0,%1,%2,%3};"
                 : "+f"(c[0]), "+f"(c[1]), "+f"(c[2]), "+f"(c[3])
                 : "r"(a[0]), "r"(a[1]), "r"(a[2]), "r"(a[3]), "r"(b[0]), "r"(b[1]));
}
__device__ __forceinline__ void cp16(unsigned dst, const void* src) {
    asm volatile("cp.async.cg.shared.global [%0], [%1], 16;" :: "r"(dst), "l"(src));
}
#define CP_COMMIT() asm volatile("cp.async.commit_group;" ::: "memory")
#define CP_WAIT(n)  asm volatile("cp.async.wait_group %0;" :: "n"(n) : "memory")

// fp16 hi/lo split of two floats, packed for half2 plane stores
__device__ __forceinline__ uint2 split2(float v0, float v1) {
    __half h0 = __float2half_rn(v0), h1 = __float2half_rn(v1);
    __half l0 = __float2half_rn(v0 - __half2float(h0));
    __half l1 = __float2half_rn(v1 - __half2float(h1));
    __half2 hh = __halves2half2(h0, h1), ll = __halves2half2(l0, l1);
    return make_uint2(*(unsigned*)&hh, *(unsigned*)&ll);
}

// ============================================================================
// Unified HMMA fp16 GEMM: D[m][n] = sum_k A[m][k] * B[n][k]  (fp32 acc)
// CFG 0: merged proj (1D grid, 768 blocks):
//        tiles [0,512): T/P  A=XT(2) B=Wt/Wp(2) K=C -> fp16 split T/P (+bias n)
//        tiles [512,768): G  A=Wg(2) B=XT(2)    K=C -> fp16 G [c][q]  (+bias m)
// CFG 2: logits  A=T(2)  B=P(2)  K=C  -> fp32 g_S
// CFG 3: AV      A=PW(1) B=G(1)  K=NS -> fp16 split Y^T [q][c]
// CFG 4: out     A=Wo(2) B=YT(2) K=C  -> fp32 d_out (+bias m, +residual)
// 128x128x32 block tile, 8 warps (2x4). 2-stage cp.async (3-stage for AV).
// ============================================================================
#define RS 20
#define TILE_U32 (128 * RS)
#define TILE_B   (TILE_U32 * 4)

template<int CFG>
__global__ void __launch_bounds__(256, 2)
mma_k(const float* __restrict__ b1, const float* __restrict__ b2,
      const float* __restrict__ b3,
      const float* __restrict__ xres, float* __restrict__ outp)
{
    constexpr int nA = (CFG == 3) ? 1 : 2;
    constexpr int nB = (CFG == 3) ? 1 : 2;
    constexpr int PLANES = nA + nB;
    constexpr int NST = (CFG == 3) ? 3 : 2;
    constexpr int STAGE_B = PLANES * TILE_B;
    const int K = (CFG == 3) ? NS : C;

    extern __shared__ unsigned su[];
    const unsigned sb = smem_u32(su);
    const int tid = threadIdx.x;
    const int wid = tid >> 5, lane = tid & 31;
    const int warp_m = wid & 1, warp_n = wid >> 1;

    const __half* Ap[2] = {nullptr, nullptr};
    const __half* Bp[2] = {nullptr, nullptr};
    int lda = C, ldb = C, batch, which = 0, m0, n0, sub = 0;

    if (CFG == 0) {
        int tile = blockIdx.x;
        if (tile < 512) {              // T/P projections
            sub = 0;
            int z = tile >> 6;         // 0..7
            batch = z >> 1; which = z & 1;
            int rem = tile & 63;
            m0 = (rem >> 1) * 128;     // 32 q-tiles
            n0 = (rem & 1) * 128;      // 2 c-tiles
            Ap[0] = g_XTh + (size_t)batch * NS * C;  Ap[1] = g_XTl + (size_t)batch * NS * C;
            Bp[0] = g_Wh + (size_t)which * C * C;    Bp[1] = g_Wl + (size_t)which * C * C;
        } else {                       // G projection
            sub = 1;
            int t = tile - 512;        // 0..255
            batch = t >> 6;
            int rem = t & 63;
            m0 = (rem >> 5) * 128;     // 2 c-tiles
            n0 = (rem & 31) * 128;     // 32 q-tiles
            Ap[0] = g_Wh + 2 * C * C;  Ap[1] = g_Wl + 2 * C * C;
            Bp[0] = g_XTh + (size_t)batch * NS * C;  Bp[1] = g_XTl + (size_t)batch * NS * C;
        }
    } else {
        batch = blockIdx.z;
        m0 = blockIdx.y * 128; n0 = blockIdx.x * 128;
        if (CFG == 2) {
            Ap[0] = g_Th + (size_t)batch * NS * C;   Ap[1] = g_Tl + (size_t)batch * NS * C;
            Bp[0] = g_Ph + (size_t)batch * NS * C;   Bp[1] = g_Pl + (size_t)batch * NS * C;
        } else if (CFG == 3) {
            Ap[0] = g_PWh + (size_t)batch * NS * NS; lda = NS;
            Bp[0] = g_Gh + (size_t)batch * C * NS;   ldb = NS;
        } else {
            Ap[0] = g_Wh + 3 * C * C;  Ap[1] = g_Wl + 3 * C * C;
            Bp[0] = g_YTh + (size_t)batch * NS * C;  Bp[1] = g_YTl + (size_t)batch * NS * C;
        }
    }

    auto issue = [&](int chunk, int buf) {
        const unsigned sbase = sb + (unsigned)buf * STAGE_B;
        const int k0 = chunk * 32;
        #pragma unroll
        for (int c = 0; c < 2; c++) {
            int idx = tid + c * 256;
            int row = idx >> 2, q = idx & 3;
            unsigned doff = (unsigned)(row * RS + q * 4) * 4;
            #pragma unroll
            for (int p = 0; p < nA; p++)
                cp16(sbase + (unsigned)(p * TILE_B) + doff,
                     Ap[p] + (size_t)(m0 + row) * lda + k0 + q * 8);
            #pragma unroll
            for (int p = 0; p < nB; p++)
                cp16(sbase + (unsigned)((nA + p) * TILE_B) + doff,
                     Bp[p] + (size_t)(n0 + row) * ldb + k0 + q * 8);
        }
    };

    float acc[4][4][4] = {};
    const int lrow = lane & 15;
    const int lkoff = (lane >> 4) * 4;
    const int nch = K / 32;

    issue(0, 0); CP_COMMIT();
    issue(1, 1); CP_COMMIT();            // nch >= 8 always

    for (int i = 0; i < nch; i++) {
        if (i == nch - 1) { CP_WAIT(0); } else { CP_WAIT(1); }
        __syncthreads();
        if (NST == 3 && i + 2 < nch) { issue(i + 2, (i + 2) % 3); CP_COMMIT(); }

        const unsigned tb = sb + (unsigned)(i % NST) * STAGE_B;
        #pragma unroll
        for (int ks = 0; ks < 2; ks++) {
            const int koff = ks * 8 + lkoff;
            unsigned bfr[nB][4][2];
            #pragma unroll
            for (int pb = 0; pb < nB; pb++) {
                #pragma unroll
                for (int np = 0; np < 2; np++) {
                    int brow = warp_n * 32 + np * 16 + lrow;
                    unsigned ad = tb + (unsigned)((nA + pb) * TILE_U32 + brow * RS + koff) * 4;
                    unsigned r0, r1, r2, r3;
                    ldsm_x4(ad, r0, r1, r2, r3);
                    bfr[pb][2*np][0] = r0; bfr[pb][2*np+1][0] = r1;
                    bfr[pb][2*np][1] = r2; bfr[pb][2*np+1][1] = r3;
                }
            }
            #pragma unroll
            for (int mf = 0; mf < 4; mf++) {
                int arow = warp_m * 64 + mf * 16 + lrow;
                unsigned afr[nA][4];
                #pragma unroll
                for (int pa = 0; pa < nA; pa++) {
                    unsigned ad = tb + (unsigned)(pa * TILE_U32 + arow * RS + koff) * 4;
                    ldsm_x4(ad, afr[pa][0], afr[pa][1], afr[pa][2], afr[pa][3]);
                }
                #pragma unroll
                for (int nf = 0; nf < 4; nf++) {
                    mma_fp16(acc[mf][nf], afr[0], bfr[0][nf]);
                    if (nA == 2 && nB == 2) {
                        mma_fp16(acc[mf][nf], afr[0], bfr[1][nf]);
                        mma_fp16(acc[mf][nf], afr[1], bfr[0][nf]);
                    }
                }
            }
        }
        __syncthreads();
        if (NST == 2 && i + 2 < nch) { issue(i + 2, i & 1); CP_COMMIT(); }
    }

    // ---- epilogue ----
    #pragma unroll
    for (int mf = 0; mf < 4; mf++) {
        int mb = m0 + warp_m * 64 + mf * 16 + (lane >> 2);
        #pragma unroll
        for (int nf = 0; nf < 4; nf++) {
            int n = n0 + warp_n * 32 + nf * 8 + (lane & 3) * 2;
            float* a4 = acc[mf][nf];
            if (CFG == 2) {
                float* D = g_S + (size_t)batch * NS * NS;
                *(float2*)&D[(size_t)mb * NS + n]       = make_float2(a4[0], a4[1]);
                *(float2*)&D[(size_t)(mb + 8) * NS + n] = make_float2(a4[2], a4[3]);
            } else if (CFG == 4) {
                float* D = outp + (size_t)batch * C * NS;
                const float* X = xres + (size_t)batch * C * NS;
                float bi0 = b1[mb], bi1 = b1[mb + 8];
                float2 x0 = *(const float2*)&X[(size_t)mb * NS + n];
                float2 x1 = *(const float2*)&X[(size_t)(mb + 8) * NS + n];
                *(float2*)&D[(size_t)mb * NS + n]       = make_float2(a4[0] + bi0 + x0.x, a4[1] + bi0 + x0.y);
                *(float2*)&D[(size_t)(mb + 8) * NS + n] = make_float2(a4[2] + bi1 + x1.x, a4[3] + bi1 + x1.y);
            } else if (CFG == 3) {   // Y^T fp16 split
                uint2 s0 = split2(a4[0], a4[1]);
                uint2 s1 = split2(a4[2], a4[3]);
                __half* Oh = g_YTh + (size_t)batch * NS * C;
                __half* Ol = g_YTl + (size_t)batch * NS * C;
                *(unsigned*)&Oh[(size_t)mb * C + n]       = s0.x;
                *(unsigned*)&Ol[(size_t)mb * C + n]       = s0.y;
                *(unsigned*)&Oh[(size_t)(mb + 8) * C + n] = s1.x;
                *(unsigned*)&Ol[(size_t)(mb + 8) * C + n] = s1.y;
            } else if (sub == 0) {   // T/P projections
                __half* Oh = (which ? g_Ph : g_Th) + (size_t)batch * NS * C;
                __half* Ol = (which ? g_Pl : g_Tl) + (size_t)batch * NS * C;
                const float* bb = which ? b2 : b1;
                float bn0 = bb[n], bn1 = bb[n + 1];
                uint2 s0 = split2(a4[0] + bn0, a4[1] + bn1);
                uint2 s1 = split2(a4[2] + bn0, a4[3] + bn1);
                *(unsigned*)&Oh[(size_t)mb * C + n]       = s0.x;
                *(unsigned*)&Ol[(size_t)mb * C + n]       = s0.y;
                *(unsigned*)&Oh[(size_t)(mb + 8) * C + n] = s1.x;
                *(unsigned*)&Ol[(size_t)(mb + 8) * C + n] = s1.y;
            } else {                 // G projection
                __half* O = g_Gh + (size_t)batch * C * NS;
                float bi0 = b3[mb], bi1 = b3[mb + 8];
                __half2 h0 = __floats2half2_rn(a4[0] + bi0, a4[1] + bi0);
                __half2 h1 = __floats2half2_rn(a4[2] + bi1, a4[3] + bi1);
                *(unsigned*)&O[(size_t)mb * NS + n]       = *(unsigned*)&h0;
                *(unsigned*)&O[(size_t)(mb + 8) * NS + n] = *(unsigned*)&h1;
            }
        }
    }
}

// ============================================================================
// x^T split: x [b][c][q] fp32 -> XTh/XTl [b][q][c] fp16. 64x64 smem tiles.
// ============================================================================
__global__ void xt_split_kernel(const float* __restrict__ x)
{
    __shared__ float tile[64][68];
    int q0 = blockIdx.x * 64, c0 = blockIdx.y * 64, b = blockIdx.z;
    int tid = threadIdx.x;
    const float* X = x + (size_t)b * C * NS;

    #pragma unroll
    for (int i = 0; i < 4; i++) {
        int c = (tid >> 4) + i * 16;
        int qq = (tid & 15) * 4;
        float4 v = *(const float4*)&X[(size_t)(c0 + c) * NS + q0 + qq];
        tile[qq + 0][c] = v.x; tile[qq + 1][c] = v.y;
        tile[qq + 2][c] = v.z; tile[qq + 3][c] = v.w;
    }
    __syncthreads();

    __half* Oh = g_XTh + (size_t)b * NS * C;
    __half* Ol = g_XTl + (size_t)b * NS * C;
    #pragma unroll
    for (int i = 0; i < 4; i++) {
        int q = (tid >> 4) + i * 16;
        int cc = (tid & 15) * 4;
        float4 v = *(const float4*)&tile[q][cc];
        uint2 s0 = split2(v.x, v.y);
        uint2 s1 = split2(v.z, v.w);
        size_t off = (size_t)(q0 + q) * C + c0 + cc;
        *(uint2*)&Oh[off] = make_uint2(s0.x, s1.x);
        *(uint2*)&Ol[off] = make_uint2(s0.y, s1.y);
    }
}

// ============================================================================
// weight split: 4 * 65536 elems = 131072 pairs -> 512 blocks x 256 threads
// ============================================================================
__global__ void wsplit_kernel(const float* __restrict__ Wt, const float* __restrict__ Wp,
                              const float* __restrict__ Wg, const float* __restrict__ Wo)
{
    int id = blockIdx.x * 256 + threadIdx.x;
    int mat = id >> 15;
    int off = (id & 32767) * 2;
    const float* W = (mat == 0) ? Wt : (mat == 1) ? Wp : (mat == 2) ? Wg : Wo;
    float2 v = *(const float2*)&W[off];
    uint2 s = split2(v.x, v.y);
    *(unsigned*)&g_Wh[mat * C * C + off] = s.x;
    *(unsigned*)&g_Wl[mat * C * C + off] = s.y;
}

// ============================================================================
// softmax: fp32 logits -> fp16 weights
// ============================================================================
__global__ void softmax_kernel()
{
    size_t row = blockIdx.x;
    const float* p = g_S + row * (size_t)NS;
    __half* po = g_PWh + row * (size_t)NS;
    int tid = threadIdx.x;
    int lane = tid & 31, wd = tid >> 5;
    __shared__ float red[8];

    float4 v[4];
    float mx = -1e30f;
    #pragma unroll
    for (int i = 0; i < 4; i++) {
        v[i] = *(const float4*)&p[(tid + i * 256) * 4];
        mx = fmaxf(mx, fmaxf(fmaxf(v[i].x, v[i].y), fmaxf(v[i].z, v[i].w)));
    }
    #pragma unroll
    for (int off = 16; off > 0; off >>= 1)
        mx = fmaxf(mx, __shfl_xor_sync(0xffffffffu, mx, off));
    if (lane == 0) red[wd] = mx;
    __syncthreads();
    mx = red[0];
    #pragma unroll
    for (int w = 1; w < 8; w++) mx = fmaxf(mx, red[w]);

    float s = 0.f;
    #pragma unroll
    for (int i = 0; i < 4; i++) {
        v[i].x = expf(v[i].x - mx); v[i].y = expf(v[i].y - mx);
        v[i].z = expf(v[i].z - mx); v[i].w = expf(v[i].w - mx);
        s += v[i].x + v[i].y + v[i].z + v[i].w;
    }
    #pragma unroll
    for (int off = 16; off > 0; off >>= 1)
        s += __shfl_xor_sync(0xffffffffu, s, off);
    __syncthreads();
    if (lane == 0) red[wd] = s;
    __syncthreads();
    s = 0.f;
    #pragma unroll
    for (int w = 0; w < 8; w++) s += red[w];
    float inv = 1.0f / s;

    #pragma unroll
    for (int i = 0; i < 4; i++) {
        __half2 h01 = __floats2half2_rn(v[i].x * inv, v[i].y * inv);
        __half2 h23 = __floats2half2_rn(v[i].z * inv, v[i].w * inv);
        uint2 o = make_uint2(*(unsigned*)&h01, *(unsigned*)&h23);
        *(uint2*)&po[(tid + i * 256) * 4] = o;
    }
}

// ============================================================================
extern "C" void kernel_launch(void* const* d_in, const int* in_sizes, int n_in,
                              void* d_out, int out_size)
{
    const float* x  = (const float*)d_in[0];
    const float* Wg = (const float*)d_in[1];
    const float* bg = (const float*)d_in[2];
    const float* Wt = (const float*)d_in[3];
    const float* bt = (const float*)d_in[4];
    const float* Wp = (const float*)d_in[5];
    const float* bp = (const float*)d_in[6];
    const float* Wo = (const float*)d_in[7];
    const float* bo = (const float*)d_in[8];
    float* out = (float*)d_out;

    const int S4 = 2 * 4 * TILE_B;   // 81920  (2-stage, 4 planes)
    const int S2 = 3 * 2 * TILE_B;   // 61440  (3-stage, 2 planes; AV)
    cudaFuncSetAttribute(mma_k<0>, cudaFuncAttributeMaxDynamicSharedMemorySize, S4);
    cudaFuncSetAttribute(mma_k<2>, cudaFuncAttributeMaxDynamicSharedMemorySize, S4);
    cudaFuncSetAttribute(mma_k<3>, cudaFuncAttributeMaxDynamicSharedMemorySize, S2);
    cudaFuncSetAttribute(mma_k<4>, cudaFuncAttributeMaxDynamicSharedMemorySize, S4);

    wsplit_kernel  <<<512, 256>>>(Wt, Wp, Wg, Wo);
    xt_split_kernel<<<dim3(NS / 64, C / 64, NB), 256>>>(x);

    mma_k<0><<<768, 256, S4>>>(bt, bp, bg, nullptr, nullptr);                    // T,P,G
    mma_k<2><<<dim3(NS / 128, NS / 128, NB), 256, S4>>>(nullptr, nullptr, nullptr, nullptr, nullptr); // logits
    softmax_kernel<<<NB * NS, 256>>>();
    mma_k<3><<<dim3(C / 128, NS / 128, NB), 256, S2>>>(nullptr, nullptr, nullptr, nullptr, nullptr);  // AV
    mma_k<4><<<dim3(NS / 128, C / 128, NB), 256, S4>>>(bo, nullptr, nullptr, x, out);                 // out
}

// round 9
// speedup vs baseline: 3.7057x; 1.1386x over previous
#include <cuda_runtime.h>
#include <cuda_fp16.h>

#define NB 4
#define C  256
#define NS 4096

// ---- device scratch (allocation-free) ----
__device__ __half g_XTh[NB * NS * C];   // x^T hi  [b][q][c]
__device__ __half g_XTl[NB * NS * C];   // x^T lo
__device__ __half g_Wh[4 * C * C];      // weights hi: Wt,Wp,Wg,Wo
__device__ __half g_Wl[4 * C * C];
__device__ __half g_Th[NB * NS * C];    // theta hi [q][c]
__device__ __half g_Tl[NB * NS * C];
__device__ __half g_Ph[NB * NS * C];    // phi hi [k'][c]
__device__ __half g_Pl[NB * NS * C];
__device__ __half g_Gh[NB * C * NS];    // g fp16 [c][q]
__device__ float  g_S [(size_t)NB * NS * NS];   // logits fp32
__device__ __half g_PWh[(size_t)NB * NS * NS];  // softmax weights fp16
__device__ __half g_YTh[NB * NS * C];   // Y^T hi [q][c]
__device__ __half g_YTl[NB * NS * C];

__device__ __forceinline__ unsigned smem_u32(const void* p) {
    unsigned a;
    asm("{ .reg .u64 t; cvta.to.shared.u64 t, %1; cvt.u32.u64 %0, t; }" : "=r"(a) : "l"(p));
    return a;
}
__device__ __forceinline__ void ldsm_x4(unsigned addr, unsigned& r0, unsigned& r1,
                                        unsigned& r2, unsigned& r3) {
    asm volatile("ldmatrix.sync.aligned.m8n8.x4.shared.b16 {%0,%1,%2,%3}, [%4];"
                 : "=r"(r0), "=r"(r1), "=r"(r2), "=r"(r3) : "r"(addr));
}
__device__ __forceinline__ void mma_fp16(float* c, const unsigned* a, const unsigned* b) {
    asm volatile("mma.sync.aligned.m16n8k16.row.col.f32.f16.f16.f32 "
                 "{%0,%1,%2,%3}, {%4,%5,%6,%7}, {%8,%9}, {%0,%1,%2,%3};"
                 : "+f"(c[0]), "+f"(c[1]), "+f"(c[2]), "+f"(c[3])
                 : "r"(a[0]), "r"(a[1]), "r"(a[2]), "r"(a[3]), "r"(b[0]), "r"(b[1]));
}
__device__ __forceinline__ void cp16(unsigned dst, const void* src) {
    asm volatile("cp.async.cg.shared.global [%0], [%1], 16;" :: "r"(dst), "l"(src));
}
#define CP_COMMIT() asm volatile("cp.async.commit_group;" ::: "memory")
#define CP_WAIT(n)  asm volatile("cp.async.wait_group %0;" :: "n"(n) : "memory")

// fp16 hi/lo split of two floats, packed for half2 plane stores
__device__ __forceinline__ uint2 split2(float v0, float v1) {
    __half h0 = __float2half_rn(v0), h1 = __float2half_rn(v1);
    __half l0 = __float2half_rn(v0 - __half2float(h0));
    __half l1 = __float2half_rn(v1 - __half2float(h1));
    __half2 hh = __halves2half2(h0, h1), ll = __halves2half2(l0, l1);
    return make_uint2(*(unsigned*)&hh, *(unsigned*)&ll);
}

// tile: 128 rows x 64B (32 fp16), XOR-swizzled 16B chunks: phys = q ^ ((row>>1)&3)
#define TILE_B 8192
__device__ __forceinline__ unsigned sw_off(int row, int q16) {
    return (unsigned)(row * 64 + ((q16 ^ ((row >> 1) & 3)) << 4));
}

// ============================================================================
// Unified HMMA fp16 GEMM: D[m][n] = sum_k A[m][k] * B[n][k]  (fp32 acc)
// CFG 0: merged proj (1D grid 768): [0,512) T/P ; [512,768) G
// CFG 2: logits  A=T(2)  B=P(2)  K=C  -> fp32 g_S
// CFG 3: AV      A=PW(1) B=G(1)  K=NS -> fp16 split Y^T [q][c]
// CFG 4: out     A=Wo(2) B=YT(2) K=C  -> fp32 d_out (+bias m, +residual)
// 128x128x32 block tile, 8 warps (2x4). NST-stage cp.async, ONE barrier/chunk.
// ============================================================================
template<int CFG>
__global__ void __launch_bounds__(256, 2)
mma_k(const float* __restrict__ b1, const float* __restrict__ b2,
      const float* __restrict__ b3,
      const float* __restrict__ xres, float* __restrict__ outp)
{
    constexpr int nA = (CFG == 3) ? 1 : 2;
    constexpr int nB = (CFG == 3) ? 1 : 2;
    constexpr int PLANES = nA + nB;
    constexpr int NST = (CFG == 3) ? 4 : 3;
    constexpr int STAGE_B = PLANES * TILE_B;
    const int K = (CFG == 3) ? NS : C;

    extern __shared__ unsigned su[];
    const unsigned sb = smem_u32(su);
    const int tid = threadIdx.x;
    const int wid = tid >> 5, lane = tid & 31;
    const int warp_m = wid & 1, warp_n = wid >> 1;

    const __half* Ap[2] = {nullptr, nullptr};
    const __half* Bp[2] = {nullptr, nullptr};
    int lda = C, ldb = C, batch, which = 0, m0, n0, sub = 0;

    if (CFG == 0) {
        int tile = blockIdx.x;
        if (tile < 512) {              // T/P projections
            sub = 0;
            int z = tile >> 6;
            batch = z >> 1; which = z & 1;
            int rem = tile & 63;
            m0 = (rem >> 1) * 128;
            n0 = (rem & 1) * 128;
            Ap[0] = g_XTh + (size_t)batch * NS * C;  Ap[1] = g_XTl + (size_t)batch * NS * C;
            Bp[0] = g_Wh + (size_t)which * C * C;    Bp[1] = g_Wl + (size_t)which * C * C;
        } else {                       // G projection
            sub = 1;
            int t = tile - 512;
            batch = t >> 6;
            int rem = t & 63;
            m0 = (rem >> 5) * 128;
            n0 = (rem & 31) * 128;
            Ap[0] = g_Wh + 2 * C * C;  Ap[1] = g_Wl + 2 * C * C;
            Bp[0] = g_XTh + (size_t)batch * NS * C;  Bp[1] = g_XTl + (size_t)batch * NS * C;
        }
    } else {
        batch = blockIdx.z;
        m0 = blockIdx.y * 128; n0 = blockIdx.x * 128;
        if (CFG == 2) {
            Ap[0] = g_Th + (size_t)batch * NS * C;   Ap[1] = g_Tl + (size_t)batch * NS * C;
            Bp[0] = g_Ph + (size_t)batch * NS * C;   Bp[1] = g_Pl + (size_t)batch * NS * C;
        } else if (CFG == 3) {
            Ap[0] = g_PWh + (size_t)batch * NS * NS; lda = NS;
            Bp[0] = g_Gh + (size_t)batch * C * NS;   ldb = NS;
        } else {
            Ap[0] = g_Wh + 3 * C * C;  Ap[1] = g_Wl + 3 * C * C;
            Bp[0] = g_YTh + (size_t)batch * NS * C;  Bp[1] = g_YTl + (size_t)batch * NS * C;
        }
    }

    auto issue = [&](int chunk, int buf) {
        const unsigned sbase = sb + (unsigned)buf * STAGE_B;
        const int k0 = chunk * 32;
        #pragma unroll
        for (int c = 0; c < 2; c++) {
            int idx = tid + c * 256;
            int row = idx >> 2, q = idx & 3;
            unsigned doff = sw_off(row, q);
            #pragma unroll
            for (int p = 0; p < nA; p++)
                cp16(sbase + (unsigned)(p * TILE_B) + doff,
                     Ap[p] + (size_t)(m0 + row) * lda + k0 + q * 8);
            #pragma unroll
            for (int p = 0; p < nB; p++)
                cp16(sbase + (unsigned)((nA + p) * TILE_B) + doff,
                     Bp[p] + (size_t)(n0 + row) * ldb + k0 + q * 8);
        }
    };

    float acc[4][4][4] = {};
    const int lrow = lane & 15;
    const int lq   = lane >> 4;     // 16B half selector within 32B k-chunk
    const int nch = K / 32;

    issue(0, 0); CP_COMMIT();
    issue(1, 1); CP_COMMIT();
    if (NST == 4) { issue(2, 2); CP_COMMIT(); }

    for (int i = 0; i < nch; i++) {
        if (i >= nch - 1)                  { CP_WAIT(0); }
        else if (NST == 4 && i >= nch - 2) { CP_WAIT(1); }
        else if (NST == 4)                 { CP_WAIT(2); }
        else                               { CP_WAIT(1); }
        __syncthreads();
        if (i + NST - 1 < nch) { issue(i + NST - 1, (i + NST - 1) % NST); CP_COMMIT(); }

        const unsigned tb = sb + (unsigned)(i % NST) * STAGE_B;
        #pragma unroll
        for (int ks = 0; ks < 2; ks++) {
            const int c16 = ks * 2 + lq;
            unsigned bfr[nB][4][2];
            #pragma unroll
            for (int pb = 0; pb < nB; pb++) {
                #pragma unroll
                for (int np = 0; np < 2; np++) {
                    int brow = warp_n * 32 + np * 16 + lrow;
                    unsigned ad = tb + (unsigned)((nA + pb) * TILE_B) + sw_off(brow, c16);
                    unsigned r0, r1, r2, r3;
                    ldsm_x4(ad, r0, r1, r2, r3);
                    bfr[pb][2*np][0] = r0; bfr[pb][2*np+1][0] = r1;
                    bfr[pb][2*np][1] = r2; bfr[pb][2*np+1][1] = r3;
                }
            }
            #pragma unroll
            for (int mf = 0; mf < 4; mf++) {
                int arow = warp_m * 64 + mf * 16 + lrow;
                unsigned afr[nA][4];
                #pragma unroll
                for (int pa = 0; pa < nA; pa++) {
                    unsigned ad = tb + (unsigned)(pa * TILE_B) + sw_off(arow, c16);
                    ldsm_x4(ad, afr[pa][0], afr[pa][1], afr[pa][2], afr[pa][3]);
                }
                #pragma unroll
                for (int nf = 0; nf < 4; nf++) {
                    mma_fp16(acc[mf][nf], afr[0], bfr[0][nf]);
                    if (nA == 2 && nB == 2) {
                        mma_fp16(acc[mf][nf], afr[0], bfr[1][nf]);
                        mma_fp16(acc[mf][nf], afr[1], bfr[0][nf]);
                    }
                }
            }
        }
    }

    // ---- epilogue ----
    #pragma unroll
    for (int mf = 0; mf < 4; mf++) {
        int mb = m0 + warp_m * 64 + mf * 16 + (lane >> 2);
        #pragma unroll
        for (int nf = 0; nf < 4; nf++) {
            int n = n0 + warp_n * 32 + nf * 8 + (lane & 3) * 2;
            float* a4 = acc[mf][nf];
            if (CFG == 2) {
                float* D = g_S + (size_t)batch * NS * NS;
                *(float2*)&D[(size_t)mb * NS + n]       = make_float2(a4[0], a4[1]);
                *(float2*)&D[(size_t)(mb + 8) * NS + n] = make_float2(a4[2], a4[3]);
            } else if (CFG == 4) {
                float* D = outp + (size_t)batch * C * NS;
                const float* X = xres + (size_t)batch * C * NS;
                float bi0 = b1[mb], bi1 = b1[mb + 8];
                float2 x0 = *(const float2*)&X[(size_t)mb * NS + n];
                float2 x1 = *(const float2*)&X[(size_t)(mb + 8) * NS + n];
                *(float2*)&D[(size_t)mb * NS + n]       = make_float2(a4[0] + bi0 + x0.x, a4[1] + bi0 + x0.y);
                *(float2*)&D[(size_t)(mb + 8) * NS + n] = make_float2(a4[2] + bi1 + x1.x, a4[3] + bi1 + x1.y);
            } else if (CFG == 3) {   // Y^T fp16 split
                uint2 s0 = split2(a4[0], a4[1]);
                uint2 s1 = split2(a4[2], a4[3]);
                __half* Oh = g_YTh + (size_t)batch * NS * C;
                __half* Ol = g_YTl + (size_t)batch * NS * C;
                *(unsigned*)&Oh[(size_t)mb * C + n]       = s0.x;
                *(unsigned*)&Ol[(size_t)mb * C + n]       = s0.y;
                *(unsigned*)&Oh[(size_t)(mb + 8) * C + n] = s1.x;
                *(unsigned*)&Ol[(size_t)(mb + 8) * C + n] = s1.y;
            } else if (sub == 0) {   // T/P projections
                __half* Oh = (which ? g_Ph : g_Th) + (size_t)batch * NS * C;
                __half* Ol = (which ? g_Pl : g_Tl) + (size_t)batch * NS * C;
                const float* bb = which ? b2 : b1;
                float bn0 = bb[n], bn1 = bb[n + 1];
                uint2 s0 = split2(a4[0] + bn0, a4[1] + bn1);
                uint2 s1 = split2(a4[2] + bn0, a4[3] + bn1);
                *(unsigned*)&Oh[(size_t)mb * C + n]       = s0.x;
                *(unsigned*)&Ol[(size_t)mb * C + n]       = s0.y;
                *(unsigned*)&Oh[(size_t)(mb + 8) * C + n] = s1.x;
                *(unsigned*)&Ol[(size_t)(mb + 8) * C + n] = s1.y;
            } else {                 // G projection
                __half* O = g_Gh + (size_t)batch * C * NS;
                float bi0 = b3[mb], bi1 = b3[mb + 8];
                __half2 h0 = __floats2half2_rn(a4[0] + bi0, a4[1] + bi0);
                __half2 h1 = __floats2half2_rn(a4[2] + bi1, a4[3] + bi1);
                *(unsigned*)&O[(size_t)mb * NS + n]       = *(unsigned*)&h0;
                *(unsigned*)&O[(size_t)(mb + 8) * NS + n] = *(unsigned*)&h1;
            }
        }
    }
}

// ============================================================================
// x^T split: x [b][c][q] fp32 -> XTh/XTl [b][q][c] fp16. 64x64 smem tiles.
// ============================================================================
__global__ void xt_split_kernel(const float* __restrict__ x)
{
    __shared__ float tile[64][68];
    int q0 = blockIdx.x * 64, c0 = blockIdx.y * 64, b = blockIdx.z;
    int tid = threadIdx.x;
    const float* X = x + (size_t)b * C * NS;

    #pragma unroll
    for (int i = 0; i < 4; i++) {
        int c = (tid >> 4) + i * 16;
        int qq = (tid & 15) * 4;
        float4 v = *(const float4*)&X[(size_t)(c0 + c) * NS + q0 + qq];
        tile[qq + 0][c] = v.x; tile[qq + 1][c] = v.y;
        tile[qq + 2][c] = v.z; tile[qq + 3][c] = v.w;
    }
    __syncthreads();

    __half* Oh = g_XTh + (size_t)b * NS * C;
    __half* Ol = g_XTl + (size_t)b * NS * C;
    #pragma unroll
    for (int i = 0; i < 4; i++) {
        int q = (tid >> 4) + i * 16;
        int cc = (tid & 15) * 4;
        float4 v = *(const float4*)&tile[q][cc];
        uint2 s0 = split2(v.x, v.y);
        uint2 s1 = split2(v.z, v.w);
        size_t off = (size_t)(q0 + q) * C + c0 + cc;
        *(uint2*)&Oh[off] = make_uint2(s0.x, s1.x);
        *(uint2*)&Ol[off] = make_uint2(s0.y, s1.y);
    }
}

// ============================================================================
// weight split: 131072 pairs -> 512 blocks x 256 threads
// ============================================================================
__global__ void wsplit_kernel(const float* __restrict__ Wt, const float* __restrict__ Wp,
                              const float* __restrict__ Wg, const float* __restrict__ Wo)
{
    int id = blockIdx.x * 256 + threadIdx.x;
    int mat = id >> 15;
    int off = (id & 32767) * 2;
    const float* W = (mat == 0) ? Wt : (mat == 1) ? Wp : (mat == 2) ? Wg : Wo;
    float2 v = *(const float2*)&W[off];
    uint2 s = split2(v.x, v.y);
    *(unsigned*)&g_Wh[mat * C * C + off] = s.x;
    *(unsigned*)&g_Wl[mat * C * C + off] = s.y;
}

// ============================================================================
// softmax: fp32 logits -> fp16 weights
// ============================================================================
__global__ void softmax_kernel()
{
    size_t row = blockIdx.x;
    const float* p = g_S + row * (size_t)NS;
    __half* po = g_PWh + row * (size_t)NS;
    int tid = threadIdx.x;
    int lane = tid & 31, wd = tid >> 5;
    __shared__ float red[8];

    float4 v[4];
    float mx = -1e30f;
    #pragma unroll
    for (int i = 0; i < 4; i++) {
        v[i] = *(const float4*)&p[(tid + i * 256) * 4];
        mx = fmaxf(mx, fmaxf(fmaxf(v[i].x, v[i].y), fmaxf(v[i].z, v[i].w)));
    }
    #pragma unroll
    for (int off = 16; off > 0; off >>= 1)
        mx = fmaxf(mx, __shfl_xor_sync(0xffffffffu, mx, off));
    if (lane == 0) red[wd] = mx;
    __syncthreads();
    mx = red[0];
    #pragma unroll
    for (int w = 1; w < 8; w++) mx = fmaxf(mx, red[w]);

    float s = 0.f;
    #pragma unroll
    for (int i = 0; i < 4; i++) {
        v[i].x = expf(v[i].x - mx); v[i].y = expf(v[i].y - mx);
        v[i].z = expf(v[i].z - mx); v[i].w = expf(v[i].w - mx);
        s += v[i].x + v[i].y + v[i].z + v[i].w;
    }
    #pragma unroll
    for (int off = 16; off > 0; off >>= 1)
        s += __shfl_xor_sync(0xffffffffu, s, off);
    __syncthreads();
    if (lane == 0) red[wd] = s;
    __syncthreads();
    s = 0.f;
    #pragma unroll
    for (int w = 0; w < 8; w++) s += red[w];
    float inv = 1.0f / s;

    #pragma unroll
    for (int i = 0; i < 4; i++) {
        __half2 h01 = __floats2half2_rn(v[i].x * inv, v[i].y * inv);
        __half2 h23 = __floats2half2_rn(v[i].z * inv, v[i].w * inv);
        uint2 o = make_uint2(*(unsigned*)&h01, *(unsigned*)&h23);
        *(uint2*)&po[(tid + i * 256) * 4] = o;
    }
}

// ============================================================================
extern "C" void kernel_launch(void* const* d_in, const int* in_sizes, int n_in,
                              void* d_out, int out_size)
{
    const float* x  = (const float*)d_in[0];
    const float* Wg = (const float*)d_in[1];
    const float* bg = (const float*)d_in[2];
    const float* Wt = (const float*)d_in[3];
    const float* bt = (const float*)d_in[4];
    const float* Wp = (const float*)d_in[5];
    const float* bp = (const float*)d_in[6];
    const float* Wo = (const float*)d_in[7];
    const float* bo = (const float*)d_in[8];
    float* out = (float*)d_out;

    const int S4 = 3 * 4 * TILE_B;   // 98304  (3-stage, 4 planes)
    const int S2 = 4 * 2 * TILE_B;   // 65536  (4-stage, 2 planes; AV)
    cudaFuncSetAttribute(mma_k<0>, cudaFuncAttributeMaxDynamicSharedMemorySize, S4);
    cudaFuncSetAttribute(mma_k<2>, cudaFuncAttributeMaxDynamicSharedMemorySize, S4);
    cudaFuncSetAttribute(mma_k<3>, cudaFuncAttributeMaxDynamicSharedMemorySize, S2);
    cudaFuncSetAttribute(mma_k<4>, cudaFuncAttributeMaxDynamicSharedMemorySize, S4);

    wsplit_kernel  <<<512, 256>>>(Wt, Wp, Wg, Wo);
    xt_split_kernel<<<dim3(NS / 64, C / 64, NB), 256>>>(x);

    mma_k<0><<<768, 256, S4>>>(bt, bp, bg, nullptr, nullptr);                    // T,P,G
    mma_k<2><<<dim3(NS / 128, NS / 128, NB), 256, S4>>>(nullptr, nullptr, nullptr, nullptr, nullptr); // logits
    softmax_kernel<<<NB * NS, 256>>>();
    mma_k<3><<<dim3(C / 128, NS / 128, NB), 256, S2>>>(nullptr, nullptr, nullptr, nullptr, nullptr);  // AV
    mma_k<4><<<dim3(NS / 128, C / 128, NB), 256, S4>>>(bo, nullptr, nullptr, x, out);                 // out
}